// round 10
// baseline (speedup 1.0000x reference)
#include <cuda_runtime.h>
#include <cuda_bf16.h>
#include <stdint.h>

#define DM 1024
#define NH 16
#define DK 64
#define SEQ 2048
#define MTOT 4096
#define NBH 32
#define NX (MTOT*DM)
#define NW (DM*DM)

// scratch arena
__device__ __nv_bfloat16 g_buf[14ull*NX + 8ull*NW];

#define OFF_XQH 0ull
#define OFF_XQL (1ull*NX)
#define OFF_XKH (2ull*NX)
#define OFF_XKL (3ull*NX)
#define OFF_XVH (4ull*NX)
#define OFF_XVL (5ull*NX)
#define OFF_W   (6ull*NX)
#define OFF_QH  (OFF_W + 8ull*NW)
#define OFF_QL  (OFF_QH + 1ull*NX)
#define OFF_KH  (OFF_QH + 2ull*NX)
#define OFF_KL  (OFF_QH + 3ull*NX)
#define OFF_VH  (OFF_QH + 4ull*NX)   /* transposed [b,h,d,s] */
#define OFF_VL  (OFF_QH + 5ull*NX)
#define OFF_CH  (OFF_QH + 6ull*NX)
#define OFF_CL  (OFF_QH + 7ull*NX)

static __device__ __forceinline__ uint32_t smem_u32(const void* p) {
    uint32_t a;
    asm("{ .reg .u64 t; cvta.to.shared.u64 t, %1; cvt.u32.u64 %0, t; }" : "=r"(a) : "l"(p));
    return a;
}

#define MMA(C, A, B) asm volatile( \
    "mma.sync.aligned.m16n8k16.row.col.f32.bf16.bf16.f32 " \
    "{%0,%1,%2,%3}, {%4,%5,%6,%7}, {%8,%9}, {%0,%1,%2,%3};" \
    : "+f"((C)[0]), "+f"((C)[1]), "+f"((C)[2]), "+f"((C)[3]) \
    : "r"((A)[0]), "r"((A)[1]), "r"((A)[2]), "r"((A)[3]), \
      "r"((B)[0]), "r"((B)[1]))

#define LDM4(R, ADDR) asm volatile( \
    "ldmatrix.sync.aligned.m8n8.x4.shared.b16 {%0,%1,%2,%3}, [%4];" \
    : "=r"((R)[0]), "=r"((R)[1]), "=r"((R)[2]), "=r"((R)[3]) : "r"(ADDR))

#define CP16(d, s) asm volatile("cp.async.cg.shared.global [%0], [%1], 16;" :: "r"(d), "l"(s))
#define CPC()   asm volatile("cp.async.commit_group;")
#define CPW(n)  asm volatile("cp.async.wait_group %0;" :: "n"(n))

// swizzles (byte offsets). SWC: 64B rows (4x16B chunks). SWK: 128B rows (8x16B chunks).
#define SWC(row, ch) (((row) << 6) + ((((ch) ^ (((row) >> 1) & 3))) << 4))
#define SWK(row, ch) (((row) << 7) + ((((ch) ^ ((row) & 7))) << 4))

static __device__ __forceinline__ void split2(float x0, float x1,
                                              uint32_t& hp, uint32_t& lp) {
    __nv_bfloat16 h0 = __float2bfloat16(x0), h1 = __float2bfloat16(x1);
    __nv_bfloat16 l0 = __float2bfloat16(x0 - __bfloat162float(h0));
    __nv_bfloat16 l1 = __float2bfloat16(x1 - __bfloat162float(h1));
    hp = (uint32_t)__bfloat16_as_ushort(h0) | ((uint32_t)__bfloat16_as_ushort(h1) << 16);
    lp = (uint32_t)__bfloat16_as_ushort(l0) | ((uint32_t)__bfloat16_as_ushort(l1) << 16);
}

// ---------------------------------------------------------------------------
struct SplitArgs {
    const float4* s[4];
    uint4* h[4];
    uint4* l[4];
};
__global__ void split_multi(SplitArgs a, int nchunks)
{
    const int y = blockIdx.y;
    const float4* src = a.s[y];
    uint4* hi = a.h[y];
    uint4* lo = a.l[y];
    int i = blockIdx.x * blockDim.x + threadIdx.x;
    if (i >= nchunks) return;
    float4 p = src[i*2], q = src[i*2+1];
    float v[8] = {p.x, p.y, p.z, p.w, q.x, q.y, q.z, q.w};
    uint4 H, L;
    split2(v[0], v[1], H.x, L.x);
    split2(v[2], v[3], H.y, L.y);
    split2(v[4], v[5], H.z, L.z);
    split2(v[6], v[7], H.w, L.w);
    hi[i] = H;
    lo[i] = L;
}

// ---------------------------------------------------------------------------
// Batched GEMM: Y = A @ W^T + bias, gridDim.z selects the problem.
// CTA 256x128, k-step 64 (two 32-k sub-blocks), 2-stage, 1 sync/iter.
// ---------------------------------------------------------------------------
struct GemmArgs {
    const __nv_bfloat16* ah[3];
    const __nv_bfloat16* al[3];
    const __nv_bfloat16* wh[3];
    const __nv_bfloat16* wl[3];
    const float* bias[3];
    float* yf[3];
    __nv_bfloat16* yh[3];
    __nv_bfloat16* yl[3];
    int mode[3];
};
#define G_SUB    49152
#define G_STAGE  98304
#define GEMM_SMEM (2*G_STAGE)
__global__ void __launch_bounds__(256, 1) gemm_mma(GemmArgs ga)
{
    extern __shared__ char sm[];
    const uint32_t sb = smem_u32(sm);
    const int z = blockIdx.z;
    const int t = threadIdx.x, lane = t & 31, w = t >> 5;
    const int wm = w & 3, wn = w >> 2;
    const int n0 = blockIdx.x * 128, m0 = blockIdx.y * 256;
    const int mode = ga.mode[z];
    const float* bias = ga.bias[z];

    const __nv_bfloat16* aSrc[2] = { ga.ah[z] + (size_t)m0 * DM, ga.al[z] + (size_t)m0 * DM };
    const __nv_bfloat16* bSrc[2] = { ga.wh[z] + (size_t)n0 * DM, ga.wl[z] + (size_t)n0 * DM };

    const int lrow = t >> 2, lch = t & 3;

#define G_LOAD(kt, st) do { \
    _Pragma("unroll") \
    for (int s_2 = 0; s_2 < 2; s_2++) { \
        _Pragma("unroll") \
        for (int p_ = 0; p_ < 2; p_++) { \
            uint32_t ab = sb + (st)*G_STAGE + s_2*G_SUB + p_*16384; \
            _Pragma("unroll") \
            for (int j_ = 0; j_ < 4; j_++) { \
                int r_ = lrow + j_*64; \
                CP16(ab + SWC(r_, lch), aSrc[p_] + (size_t)r_ * DM + (kt) + s_2*32 + lch*8); \
            } \
            uint32_t bb = sb + (st)*G_STAGE + s_2*G_SUB + 32768 + p_*8192; \
            _Pragma("unroll") \
            for (int j_ = 0; j_ < 2; j_++) { \
                int r_ = lrow + j_*64; \
                CP16(bb + SWC(r_, lch), bSrc[p_] + (size_t)r_ * DM + (kt) + s_2*32 + lch*8); \
            } \
        } \
    } \
} while (0)

    float acc[4][8][4];
    #pragma unroll
    for (int i = 0; i < 4; i++)
        #pragma unroll
        for (int j = 0; j < 8; j++)
            #pragma unroll
            for (int k = 0; k < 4; k++) acc[i][j][k] = 0.f;

    const int aRow0 = wm*64 + (lane & 15);
    const int aChH  = lane >> 4;
    const int bRowOff = wn*64 + (lane & 7) + ((lane >> 4) << 3);
    const int bChH  = (lane >> 3) & 1;

    G_LOAD(0, 0);  CPC();

    #pragma unroll 1
    for (int kc = 0; kc < 16; kc++) {
        const int st = kc & 1;
        CPW(0);
        __syncthreads();
        if (kc + 1 < 16) G_LOAD((kc + 1) * 64, st ^ 1);
        CPC();

        #pragma unroll
        for (int sub = 0; sub < 2; sub++) {
            const uint32_t uAh = sb + st*G_STAGE + sub*G_SUB;
            const uint32_t uAl = uAh + 16384;
            const uint32_t uBh = uAh + 32768;
            const uint32_t uBl = uAh + 40960;
            #pragma unroll
            for (int ks = 0; ks < 2; ks++) {
                const int c = ks*2 + aChH;
                uint32_t aF[2][4][4];
                #pragma unroll
                for (int mt = 0; mt < 4; mt++) {
                    LDM4(aF[0][mt], uAh + SWC(aRow0 + mt*16, c));
                    LDM4(aF[1][mt], uAl + SWC(aRow0 + mt*16, c));
                }
                const int cb = ks*2 + bChH;
                #pragma unroll
                for (int nt2 = 0; nt2 < 4; nt2++) {
                    int r = bRowOff + nt2*16;
                    uint32_t rh[4], rl[4];
                    LDM4(rh, uBh + SWC(r, cb));
                    LDM4(rl, uBl + SWC(r, cb));
                    uint32_t bh0[2] = {rh[0], rh[1]}, bh1[2] = {rh[2], rh[3]};
                    uint32_t bl0[2] = {rl[0], rl[1]}, bl1[2] = {rl[2], rl[3]};
                    const int nA = nt2*2, nB = nt2*2 + 1;
                    #pragma unroll
                    for (int mt = 0; mt < 4; mt++) {
                        MMA(acc[mt][nA], aF[0][mt], bh0);
                        MMA(acc[mt][nB], aF[0][mt], bh1);
                    }
                    #pragma unroll
                    for (int mt = 0; mt < 4; mt++) {
                        MMA(acc[mt][nA], aF[0][mt], bl0);
                        MMA(acc[mt][nB], aF[0][mt], bl1);
                    }
                    #pragma unroll
                    for (int mt = 0; mt < 4; mt++) {
                        MMA(acc[mt][nA], aF[1][mt], bh0);
                        MMA(acc[mt][nB], aF[1][mt], bh1);
                    }
                }
            }
        }
    }

    // ---- epilogue ----
    float* Yf = ga.yf[z];
    __nv_bfloat16* Yh = ga.yh[z];
    __nv_bfloat16* Yl = ga.yl[z];
    const int g = lane >> 2, tig = lane & 3;
    #pragma unroll
    for (int mt = 0; mt < 4; mt++) {
        const int r0 = m0 + wm*64 + mt*16 + g;
        float v[2][8][2];
        #pragma unroll
        for (int nt = 0; nt < 8; nt++) {
            int col = n0 + wn*64 + nt*8 + tig*2;
            float b0v = bias[col], b1v = bias[col + 1];
            v[0][nt][0] = acc[mt][nt][0] + b0v;
            v[0][nt][1] = acc[mt][nt][1] + b1v;
            v[1][nt][0] = acc[mt][nt][2] + b0v;
            v[1][nt][1] = acc[mt][nt][3] + b1v;
        }
        if (mode == 0) {
            #pragma unroll
            for (int rr = 0; rr < 2; rr++) {
                int r = r0 + rr*8;
                #pragma unroll
                for (int nt = 0; nt < 8; nt++) {
                    int col = n0 + wn*64 + nt*8 + tig*2;
                    *(float2*)(Yf + (size_t)r * DM + col) =
                        make_float2(v[rr][nt][0], v[rr][nt][1]);
                }
            }
        } else {
            if (mode == 3) {
                #pragma unroll
                for (int rr = 0; rr < 2; rr++) {
                    float ss = 0.f;
                    #pragma unroll
                    for (int nt = 0; nt < 8; nt++)
                        ss += v[rr][nt][0]*v[rr][nt][0] + v[rr][nt][1]*v[rr][nt][1];
                    ss += __shfl_xor_sync(0xffffffffu, ss, 1);
                    ss += __shfl_xor_sync(0xffffffffu, ss, 2);
                    float inv = rsqrtf(ss + 1e-8f);
                    #pragma unroll
                    for (int nt = 0; nt < 8; nt++) {
                        v[rr][nt][0] *= inv;
                        v[rr][nt][1] *= inv;
                    }
                }
            }
            const int h_ = (n0 >> 6) + wn;
            const int b_ = r0 >> 11;
            #pragma unroll
            for (int rr = 0; rr < 2; rr++) {
                const int s_ = (r0 + rr*8) & 2047;
                if (mode == 1) {
                    const size_t base = (size_t)(b_ * NH + h_) * DK;
                    #pragma unroll
                    for (int nt = 0; nt < 8; nt++) {
                        int d = nt*8 + tig*2;
                        float x0 = v[rr][nt][0], x1 = v[rr][nt][1];
                        __nv_bfloat16 h0 = __float2bfloat16(x0);
                        __nv_bfloat16 h1 = __float2bfloat16(x1);
                        Yh[(base + d    ) * SEQ + s_] = h0;
                        Yh[(base + d + 1) * SEQ + s_] = h1;
                        Yl[(base + d    ) * SEQ + s_] =
                            __float2bfloat16(x0 - __bfloat162float(h0));
                        Yl[(base + d + 1) * SEQ + s_] =
                            __float2bfloat16(x1 - __bfloat162float(h1));
                    }
                } else {
                    const size_t base = ((size_t)(b_ * NH + h_) * SEQ + s_) * DK;
                    #pragma unroll
                    for (int nt = 0; nt < 8; nt++) {
                        uint32_t hp, lp;
                        split2(v[rr][nt][0], v[rr][nt][1], hp, lp);
                        *(uint32_t*)(Yh + base + nt*8 + tig*2) = hp;
                        *(uint32_t*)(Yl + base + nt*8 + tig*2) = lp;
                    }
                }
            }
        }
    }
#undef G_LOAD
}

// ---------------------------------------------------------------------------
// Attention: CTA = (bh, 128-q tile), 8 warps x 16 q-rows, 64-key chunks,
// 2-stage cp.async, 1 sync/iter. Software-pipelined S/PV interleave:
// j-step issues S MMAs for key-col block j and split+PV for block j-1.
// Q hi-fragments preloaded across the whole loop.
// ---------------------------------------------------------------------------
#define A_QARR  16384                 /* 128 rows x 128B */
#define A_KARR  8192                  /* 64 rows x 128B */
#define A_STAGE (4*A_KARR)            /* 32768: Kh Kl Vh Vl */
#define A_QTOT  (2*A_QARR)            /* 32768 */
#define ATTN_SMEM (A_QTOT + 2*A_STAGE)   /* 98304 */
__global__ void __launch_bounds__(256, 2) attn_mma(
    const __nv_bfloat16* __restrict__ qhp, const __nv_bfloat16* __restrict__ qlp,
    const __nv_bfloat16* __restrict__ khp, const __nv_bfloat16* __restrict__ klp,
    const __nv_bfloat16* __restrict__ vhp, const __nv_bfloat16* __restrict__ vlp,
    __nv_bfloat16* __restrict__ ch, __nv_bfloat16* __restrict__ cl)
{
    extern __shared__ char sm[];
    const uint32_t sb = smem_u32(sm);
    const int t = threadIdx.x, lane = t & 31, w = t >> 5;
    const int q0 = blockIdx.x * 128;
    const int bh = blockIdx.y;
    const size_t base = (size_t)bh * SEQ * DK;

    const __nv_bfloat16* Ksrc[2] = { khp + base, klp + base };
    const __nv_bfloat16* Vsrc[2] = { vhp + base, vlp + base };

    const int krow = t >> 2, kch = t & 3;

#define A_LOADKV(kt, st) do { \
    _Pragma("unroll") \
    for (int p_ = 0; p_ < 2; p_++) { \
        uint32_t kb = sb + A_QTOT + (st)*A_STAGE + p_*A_KARR; \
        CP16(kb + SWK(krow, kch),     Ksrc[p_] + (size_t)((kt) + krow) * DK + kch*8); \
        CP16(kb + SWK(krow, kch + 4), Ksrc[p_] + (size_t)((kt) + krow) * DK + (kch + 4)*8); \
        uint32_t vb = sb + A_QTOT + (st)*A_STAGE + (2+p_)*A_KARR; \
        CP16(vb + SWK(krow, kch),     Vsrc[p_] + (size_t)krow * SEQ + (kt) + kch*8); \
        CP16(vb + SWK(krow, kch + 4), Vsrc[p_] + (size_t)krow * SEQ + (kt) + (kch + 4)*8); \
    } \
} while (0)

    // Q loads (group with first KV)
    {
        const __nv_bfloat16* Qsrc[2] = { qhp + base, qlp + base };
        #pragma unroll
        for (int p_ = 0; p_ < 2; p_++)
            #pragma unroll
            for (int i = 0; i < 4; i++) {
                int c = t + i*256, row = c >> 3, chn = c & 7;
                CP16(sb + p_*A_QARR + SWK(row, chn),
                     Qsrc[p_] + (size_t)(q0 + row) * DK + chn*8);
            }
    }
    A_LOADKV(0, 0);  CPC();

    const int aRow = w*16 + (lane & 15);
    const int aChH = lane >> 4;
    const int bRowOff = (lane & 7) + ((lane >> 4) << 3);
    const int bChH = (lane >> 3) & 1;

    CPW(0);
    __syncthreads();

    // Preload Q hi fragments for all 4 k-chunks (held across whole loop)
    uint32_t aQh[4][4];
    #pragma unroll
    for (int ks = 0; ks < 4; ks++)
        LDM4(aQh[ks], sb + SWK(aRow, ks*2 + aChH));

    float o[8][4];
    #pragma unroll
    for (int i = 0; i < 8; i++)
        #pragma unroll
        for (int j = 0; j < 4; j++) o[i][j] = 0.f;

    #pragma unroll 1
    for (int kc = 0; kc < 32; kc++) {
        const int st = kc & 1;
        if (kc + 1 < 32) { A_LOADKV((kc + 1) * 64, st ^ 1); CPC(); }

        const uint32_t uKh = sb + A_QTOT + st*A_STAGE;
        const uint32_t uKl = uKh + A_KARR;
        const uint32_t uVh = uKh + 2*A_KARR;
        const uint32_t uVl = uKh + 3*A_KARR;

        float s[8][4];
        #pragma unroll
        for (int i = 0; i < 8; i++)
            #pragma unroll
            for (int j2 = 0; j2 < 4; j2++) s[i][j2] = 0.f;

        // fused pipeline: step j does S(nt2=j) and split+PV(kt2=j-1)
        #pragma unroll
        for (int j = 0; j < 5; j++) {
            if (j < 4) {
                const int nt2 = j, nA = nt2*2, nB = nt2*2 + 1;
                const int r = bRowOff + nt2*16;
                #pragma unroll
                for (int ks = 0; ks < 4; ks++) {
                    const int cb = ks*2 + bChH;
                    uint32_t aQl[4];
                    LDM4(aQl, sb + A_QARR + SWK(aRow, ks*2 + aChH));
                    uint32_t rh[4], rl[4];
                    LDM4(rh, uKh + SWK(r, cb));
                    LDM4(rl, uKl + SWK(r, cb));
                    uint32_t bh0[2] = {rh[0], rh[1]}, bh1[2] = {rh[2], rh[3]};
                    uint32_t bl0[2] = {rl[0], rl[1]}, bl1[2] = {rl[2], rl[3]};
                    MMA(s[nA], aQh[ks], bh0); MMA(s[nB], aQh[ks], bh1);
                    MMA(s[nA], aQh[ks], bl0); MMA(s[nB], aQh[ks], bl1);
                    MMA(s[nA], aQl,     bh0); MMA(s[nB], aQl,     bh1);
                }
            }
            if (j >= 1) {
                const int kt2 = j - 1;
                uint32_t aPh[4], aPl[4];
                {
                    float x0, x1;
                    x0 = s[2*kt2][0]*s[2*kt2][0];     x1 = s[2*kt2][1]*s[2*kt2][1];
                    split2(x0, x1, aPh[0], aPl[0]);
                    x0 = s[2*kt2][2]*s[2*kt2][2];     x1 = s[2*kt2][3]*s[2*kt2][3];
                    split2(x0, x1, aPh[1], aPl[1]);
                    x0 = s[2*kt2+1][0]*s[2*kt2+1][0]; x1 = s[2*kt2+1][1]*s[2*kt2+1][1];
                    split2(x0, x1, aPh[2], aPl[2]);
                    x0 = s[2*kt2+1][2]*s[2*kt2+1][2]; x1 = s[2*kt2+1][3]*s[2*kt2+1][3];
                    split2(x0, x1, aPh[3], aPl[3]);
                }
                const int cb = kt2*2 + bChH;
                #pragma unroll
                for (int nt2v = 0; nt2v < 4; nt2v++) {
                    const int rv = bRowOff + nt2v*16;
                    uint32_t rh[4], rl[4];
                    LDM4(rh, uVh + SWK(rv, cb));
                    LDM4(rl, uVl + SWK(rv, cb));
                    uint32_t bh0[2] = {rh[0], rh[1]}, bh1[2] = {rh[2], rh[3]};
                    uint32_t bl0[2] = {rl[0], rl[1]}, bl1[2] = {rl[2], rl[3]};
                    const int nA = nt2v*2, nB = nt2v*2 + 1;
                    MMA(o[nA], aPh, bh0); MMA(o[nB], aPh, bh1);
                    MMA(o[nA], aPh, bl0); MMA(o[nB], aPh, bl1);
                    MMA(o[nA], aPl, bh0); MMA(o[nB], aPl, bh1);
                }
            }
        }

        CPW(0);
        __syncthreads();
    }

    // ctx epilogue: split bf16, [b, s, DM]
    const int g = lane >> 2, tig = lane & 3;
    const int r0 = q0 + w*16 + g;
    const int b_ = bh >> 4, h_ = bh & 15;
    #pragma unroll
    for (int rr = 0; rr < 2; rr++) {
        const int s_ = r0 + rr*8;
        const size_t ob = ((size_t)b_ * SEQ + s_) * DM + h_ * DK;
        #pragma unroll
        for (int nt = 0; nt < 8; nt++) {
            uint32_t hp, lp;
            split2(o[nt][rr*2], o[nt][rr*2+1], hp, lp);
            *(uint32_t*)(ch + ob + nt*8 + tig*2) = hp;
            *(uint32_t*)(cl + ob + nt*8 + tig*2) = lp;
        }
    }
#undef A_LOADKV
}

// ---------------------------------------------------------------------------
extern "C" void kernel_launch(void* const* d_in, const int* in_sizes, int n_in,
                              void* d_out, int out_size)
{
    const float* Q    = (const float*)d_in[0];
    const float* K    = (const float*)d_in[1];
    const float* V    = (const float*)d_in[2];
    const float* Wq_w = (const float*)d_in[3];
    const float* Wq_b = (const float*)d_in[4];
    const float* Wk_w = (const float*)d_in[5];
    const float* Wk_b = (const float*)d_in[6];
    const float* Wv_w = (const float*)d_in[7];
    const float* Wv_b = (const float*)d_in[8];
    const float* Wo_w = (const float*)d_in[9];
    const float* Wo_b = (const float*)d_in[10];
    float* out = (float*)d_out;

    __nv_bfloat16* gb;
    cudaGetSymbolAddress((void**)&gb, g_buf);

    __nv_bfloat16* xh[3] = { gb + OFF_XQH, gb + OFF_XKH, gb + OFF_XVH };
    __nv_bfloat16* xl[3] = { gb + OFF_XQL, gb + OFF_XKL, gb + OFF_XVL };
    __nv_bfloat16* wh[4]; __nv_bfloat16* wl[4];
    for (int i = 0; i < 4; i++) { wh[i] = gb + OFF_W + (size_t)(2*i) * NW; wl[i] = wh[i] + NW; }
    __nv_bfloat16 *qh = gb + OFF_QH, *ql = gb + OFF_QL;
    __nv_bfloat16 *kh = gb + OFF_KH, *kl = gb + OFF_KL;
    __nv_bfloat16 *vh = gb + OFF_VH, *vl = gb + OFF_VL;
    __nv_bfloat16 *ch = gb + OFF_CH, *cl = gb + OFF_CL;

    cudaFuncSetAttribute(gemm_mma, cudaFuncAttributeMaxDynamicSharedMemorySize, GEMM_SMEM);
    cudaFuncSetAttribute(attn_mma, cudaFuncAttributeMaxDynamicSharedMemorySize, ATTN_SMEM);

    SplitArgs ia;
    ia.s[0] = (const float4*)Q; ia.s[1] = (const float4*)K; ia.s[2] = (const float4*)V;
    ia.s[3] = (const float4*)Q;
    for (int i = 0; i < 3; i++) { ia.h[i] = (uint4*)xh[i]; ia.l[i] = (uint4*)xl[i]; }
    ia.h[3] = (uint4*)xh[0]; ia.l[3] = (uint4*)xl[0];
    split_multi<<<dim3(NX/8/256, 3), 256>>>(ia, NX/8);

    SplitArgs wa;
    wa.s[0] = (const float4*)Wq_w; wa.s[1] = (const float4*)Wk_w;
    wa.s[2] = (const float4*)Wv_w; wa.s[3] = (const float4*)Wo_w;
    for (int i = 0; i < 4; i++) { wa.h[i] = (uint4*)wh[i]; wa.l[i] = (uint4*)wl[i]; }
    split_multi<<<dim3(NW/8/256, 4), 256>>>(wa, NW/8);

    GemmArgs gqkv;
    gqkv.ah[0] = xh[0]; gqkv.al[0] = xl[0]; gqkv.wh[0] = wh[0]; gqkv.wl[0] = wl[0];
    gqkv.bias[0] = Wq_b; gqkv.yf[0] = nullptr; gqkv.yh[0] = qh; gqkv.yl[0] = ql; gqkv.mode[0] = 3;
    gqkv.ah[1] = xh[1]; gqkv.al[1] = xl[1]; gqkv.wh[1] = wh[1]; gqkv.wl[1] = wl[1];
    gqkv.bias[1] = Wk_b; gqkv.yf[1] = nullptr; gqkv.yh[1] = kh; gqkv.yl[1] = kl; gqkv.mode[1] = 3;
    gqkv.ah[2] = xh[2]; gqkv.al[2] = xl[2]; gqkv.wh[2] = wh[2]; gqkv.wl[2] = wl[2];
    gqkv.bias[2] = Wv_b; gqkv.yf[2] = nullptr; gqkv.yh[2] = vh; gqkv.yl[2] = vl; gqkv.mode[2] = 1;
    gemm_mma<<<dim3(DM/128, MTOT/256, 3), 256, GEMM_SMEM>>>(gqkv);

    dim3 agrid(SEQ/128, NBH);       // (16, 32) = 512 CTAs, 2/SM
    attn_mma<<<agrid, 256, ATTN_SMEM>>>(qh, ql, kh, kl, vh, vl, ch, cl);

    GemmArgs go;
    go.ah[0] = ch; go.al[0] = cl; go.wh[0] = wh[3]; go.wl[0] = wl[3];
    go.bias[0] = Wo_b; go.yf[0] = out; go.yh[0] = nullptr; go.yl[0] = nullptr; go.mode[0] = 0;
    go.ah[1] = go.ah[0]; go.al[1] = go.al[0]; go.wh[1] = go.wh[0]; go.wl[1] = go.wl[0];
    go.bias[1] = go.bias[0]; go.yf[1] = go.yf[0]; go.yh[1] = nullptr; go.yl[1] = nullptr; go.mode[1] = 0;
    go.ah[2] = go.ah[0]; go.al[2] = go.al[0]; go.wh[2] = go.wh[0]; go.wl[2] = go.wl[0];
    go.bias[2] = go.bias[0]; go.yf[2] = go.yf[0]; go.yh[2] = nullptr; go.yl[2] = nullptr; go.mode[2] = 0;
    gemm_mma<<<dim3(DM/128, MTOT/256, 1), 256, GEMM_SMEM>>>(go);
}

// round 11
// speedup vs baseline: 1.2047x; 1.2047x over previous
#include <cuda_runtime.h>
#include <cuda_bf16.h>
#include <cuda_fp16.h>
#include <stdint.h>

#define DM 1024
#define NH 16
#define DK 64
#define SEQ 2048
#define MTOT 4096
#define NBH 32
#define NX (MTOT*DM)
#define NW (DM*DM)

// scratch arena
__device__ __nv_bfloat16 g_buf[14ull*NX + 8ull*NW];

#define OFF_XQH 0ull
#define OFF_XQL (1ull*NX)
#define OFF_XKH (2ull*NX)
#define OFF_XKL (3ull*NX)
#define OFF_XVH (4ull*NX)
#define OFF_XVL (5ull*NX)
#define OFF_W   (6ull*NX)
#define OFF_QH  (OFF_W + 8ull*NW)
#define OFF_QL  (OFF_QH + 1ull*NX)
#define OFF_KH  (OFF_QH + 2ull*NX)
#define OFF_KL  (OFF_QH + 3ull*NX)
#define OFF_VF  (OFF_QH + 4ull*NX)   /* fp16 single, transposed [b,h,d,s] */
#define OFF_CH  (OFF_QH + 6ull*NX)
#define OFF_CL  (OFF_QH + 7ull*NX)

static __device__ __forceinline__ uint32_t smem_u32(const void* p) {
    uint32_t a;
    asm("{ .reg .u64 t; cvta.to.shared.u64 t, %1; cvt.u32.u64 %0, t; }" : "=r"(a) : "l"(p));
    return a;
}

#define MMA(C, A, B) asm volatile( \
    "mma.sync.aligned.m16n8k16.row.col.f32.bf16.bf16.f32 " \
    "{%0,%1,%2,%3}, {%4,%5,%6,%7}, {%8,%9}, {%0,%1,%2,%3};" \
    : "+f"((C)[0]), "+f"((C)[1]), "+f"((C)[2]), "+f"((C)[3]) \
    : "r"((A)[0]), "r"((A)[1]), "r"((A)[2]), "r"((A)[3]), \
      "r"((B)[0]), "r"((B)[1]))

#define MMAH(C, A, B) asm volatile( \
    "mma.sync.aligned.m16n8k16.row.col.f32.f16.f16.f32 " \
    "{%0,%1,%2,%3}, {%4,%5,%6,%7}, {%8,%9}, {%0,%1,%2,%3};" \
    : "+f"((C)[0]), "+f"((C)[1]), "+f"((C)[2]), "+f"((C)[3]) \
    : "r"((A)[0]), "r"((A)[1]), "r"((A)[2]), "r"((A)[3]), \
      "r"((B)[0]), "r"((B)[1]))

#define LDM4(R, ADDR) asm volatile( \
    "ldmatrix.sync.aligned.m8n8.x4.shared.b16 {%0,%1,%2,%3}, [%4];" \
    : "=r"((R)[0]), "=r"((R)[1]), "=r"((R)[2]), "=r"((R)[3]) : "r"(ADDR))

#define CP16(d, s) asm volatile("cp.async.cg.shared.global [%0], [%1], 16;" :: "r"(d), "l"(s))
#define CPC()   asm volatile("cp.async.commit_group;")
#define CPW(n)  asm volatile("cp.async.wait_group %0;" :: "n"(n))

// swizzles (byte offsets). SWC: 64B rows (4x16B chunks). SWK: 128B rows (8x16B chunks).
#define SWC(row, ch) (((row) << 6) + ((((ch) ^ (((row) >> 1) & 3))) << 4))
#define SWK(row, ch) (((row) << 7) + ((((ch) ^ ((row) & 7))) << 4))

static __device__ __forceinline__ void split2(float x0, float x1,
                                              uint32_t& hp, uint32_t& lp) {
    __nv_bfloat16 h0 = __float2bfloat16(x0), h1 = __float2bfloat16(x1);
    __nv_bfloat16 l0 = __float2bfloat16(x0 - __bfloat162float(h0));
    __nv_bfloat16 l1 = __float2bfloat16(x1 - __bfloat162float(h1));
    hp = (uint32_t)__bfloat16_as_ushort(h0) | ((uint32_t)__bfloat16_as_ushort(h1) << 16);
    lp = (uint32_t)__bfloat16_as_ushort(l0) | ((uint32_t)__bfloat16_as_ushort(l1) << 16);
}

static __device__ __forceinline__ uint32_t pack_h2(float x0, float x1) {
    __half2 h = __floats2half2_rn(x0, x1);
    return *(uint32_t*)&h;
}

// ---------------------------------------------------------------------------
struct SplitArgs {
    const float4* s[4];
    uint4* h[4];
    uint4* l[4];
};
__global__ void split_multi(SplitArgs a, int nchunks)
{
    const int y = blockIdx.y;
    const float4* src = a.s[y];
    uint4* hi = a.h[y];
    uint4* lo = a.l[y];
    int i = blockIdx.x * blockDim.x + threadIdx.x;
    if (i >= nchunks) return;
    float4 p = src[i*2], q = src[i*2+1];
    float v[8] = {p.x, p.y, p.z, p.w, q.x, q.y, q.z, q.w};
    uint4 H, L;
    split2(v[0], v[1], H.x, L.x);
    split2(v[2], v[3], H.y, L.y);
    split2(v[4], v[5], H.z, L.z);
    split2(v[6], v[7], H.w, L.w);
    hi[i] = H;
    lo[i] = L;
}

// ---------------------------------------------------------------------------
// Batched GEMM: Y = A @ W^T + bias, gridDim.z selects the problem.
// CTA 256x128, k-step 64 (two 32-k sub-blocks), 2-stage, 1 sync/iter.
// mode 0: fp32 out. mode 1: fp16 SINGLE transposed [b,h,d,s] (V).
// mode 3: bf16 split head-major + rownorm (Q,K).
// ---------------------------------------------------------------------------
struct GemmArgs {
    const __nv_bfloat16* ah[3];
    const __nv_bfloat16* al[3];
    const __nv_bfloat16* wh[3];
    const __nv_bfloat16* wl[3];
    const float* bias[3];
    float* yf[3];
    __nv_bfloat16* yh[3];
    __nv_bfloat16* yl[3];
    int mode[3];
};
#define G_SUB    49152
#define G_STAGE  98304
#define GEMM_SMEM (2*G_STAGE)
__global__ void __launch_bounds__(256, 1) gemm_mma(GemmArgs ga)
{
    extern __shared__ char sm[];
    const uint32_t sb = smem_u32(sm);
    const int z = blockIdx.z;
    const int t = threadIdx.x, lane = t & 31, w = t >> 5;
    const int wm = w & 3, wn = w >> 2;
    const int n0 = blockIdx.x * 128, m0 = blockIdx.y * 256;
    const int mode = ga.mode[z];
    const float* bias = ga.bias[z];

    const __nv_bfloat16* aSrc[2] = { ga.ah[z] + (size_t)m0 * DM, ga.al[z] + (size_t)m0 * DM };
    const __nv_bfloat16* bSrc[2] = { ga.wh[z] + (size_t)n0 * DM, ga.wl[z] + (size_t)n0 * DM };

    const int lrow = t >> 2, lch = t & 3;

#define G_LOAD(kt, st) do { \
    _Pragma("unroll") \
    for (int s_2 = 0; s_2 < 2; s_2++) { \
        _Pragma("unroll") \
        for (int p_ = 0; p_ < 2; p_++) { \
            uint32_t ab = sb + (st)*G_STAGE + s_2*G_SUB + p_*16384; \
            _Pragma("unroll") \
            for (int j_ = 0; j_ < 4; j_++) { \
                int r_ = lrow + j_*64; \
                CP16(ab + SWC(r_, lch), aSrc[p_] + (size_t)r_ * DM + (kt) + s_2*32 + lch*8); \
            } \
            uint32_t bb = sb + (st)*G_STAGE + s_2*G_SUB + 32768 + p_*8192; \
            _Pragma("unroll") \
            for (int j_ = 0; j_ < 2; j_++) { \
                int r_ = lrow + j_*64; \
                CP16(bb + SWC(r_, lch), bSrc[p_] + (size_t)r_ * DM + (kt) + s_2*32 + lch*8); \
            } \
        } \
    } \
} while (0)

    float acc[4][8][4];
    #pragma unroll
    for (int i = 0; i < 4; i++)
        #pragma unroll
        for (int j = 0; j < 8; j++)
            #pragma unroll
            for (int k = 0; k < 4; k++) acc[i][j][k] = 0.f;

    const int aRow0 = wm*64 + (lane & 15);
    const int aChH  = lane >> 4;
    const int bRowOff = wn*64 + (lane & 7) + ((lane >> 4) << 3);
    const int bChH  = (lane >> 3) & 1;

    G_LOAD(0, 0);  CPC();

    #pragma unroll 1
    for (int kc = 0; kc < 16; kc++) {
        const int st = kc & 1;
        CPW(0);
        __syncthreads();
        if (kc + 1 < 16) G_LOAD((kc + 1) * 64, st ^ 1);
        CPC();

        #pragma unroll
        for (int sub = 0; sub < 2; sub++) {
            const uint32_t uAh = sb + st*G_STAGE + sub*G_SUB;
            const uint32_t uAl = uAh + 16384;
            const uint32_t uBh = uAh + 32768;
            const uint32_t uBl = uAh + 40960;
            #pragma unroll
            for (int ks = 0; ks < 2; ks++) {
                const int c = ks*2 + aChH;
                uint32_t aF[2][4][4];
                #pragma unroll
                for (int mt = 0; mt < 4; mt++) {
                    LDM4(aF[0][mt], uAh + SWC(aRow0 + mt*16, c));
                    LDM4(aF[1][mt], uAl + SWC(aRow0 + mt*16, c));
                }
                const int cb = ks*2 + bChH;
                #pragma unroll
                for (int nt2 = 0; nt2 < 4; nt2++) {
                    int r = bRowOff + nt2*16;
                    uint32_t rh[4], rl[4];
                    LDM4(rh, uBh + SWC(r, cb));
                    LDM4(rl, uBl + SWC(r, cb));
                    uint32_t bh0[2] = {rh[0], rh[1]}, bh1[2] = {rh[2], rh[3]};
                    uint32_t bl0[2] = {rl[0], rl[1]}, bl1[2] = {rl[2], rl[3]};
                    const int nA = nt2*2, nB = nt2*2 + 1;
                    #pragma unroll
                    for (int mt = 0; mt < 4; mt++) {
                        MMA(acc[mt][nA], aF[0][mt], bh0);
                        MMA(acc[mt][nB], aF[0][mt], bh1);
                    }
                    #pragma unroll
                    for (int mt = 0; mt < 4; mt++) {
                        MMA(acc[mt][nA], aF[0][mt], bl0);
                        MMA(acc[mt][nB], aF[0][mt], bl1);
                    }
                    #pragma unroll
                    for (int mt = 0; mt < 4; mt++) {
                        MMA(acc[mt][nA], aF[1][mt], bh0);
                        MMA(acc[mt][nB], aF[1][mt], bh1);
                    }
                }
            }
        }
    }

    // ---- epilogue ----
    float* Yf = ga.yf[z];
    __nv_bfloat16* Yh = ga.yh[z];
    __nv_bfloat16* Yl = ga.yl[z];
    const int g = lane >> 2, tig = lane & 3;
    #pragma unroll
    for (int mt = 0; mt < 4; mt++) {
        const int r0 = m0 + wm*64 + mt*16 + g;
        float v[2][8][2];
        #pragma unroll
        for (int nt = 0; nt < 8; nt++) {
            int col = n0 + wn*64 + nt*8 + tig*2;
            float b0v = bias[col], b1v = bias[col + 1];
            v[0][nt][0] = acc[mt][nt][0] + b0v;
            v[0][nt][1] = acc[mt][nt][1] + b1v;
            v[1][nt][0] = acc[mt][nt][2] + b0v;
            v[1][nt][1] = acc[mt][nt][3] + b1v;
        }
        if (mode == 0) {
            #pragma unroll
            for (int rr = 0; rr < 2; rr++) {
                int r = r0 + rr*8;
                #pragma unroll
                for (int nt = 0; nt < 8; nt++) {
                    int col = n0 + wn*64 + nt*8 + tig*2;
                    *(float2*)(Yf + (size_t)r * DM + col) =
                        make_float2(v[rr][nt][0], v[rr][nt][1]);
                }
            }
        } else {
            if (mode == 3) {
                #pragma unroll
                for (int rr = 0; rr < 2; rr++) {
                    float ss = 0.f;
                    #pragma unroll
                    for (int nt = 0; nt < 8; nt++)
                        ss += v[rr][nt][0]*v[rr][nt][0] + v[rr][nt][1]*v[rr][nt][1];
                    ss += __shfl_xor_sync(0xffffffffu, ss, 1);
                    ss += __shfl_xor_sync(0xffffffffu, ss, 2);
                    float inv = rsqrtf(ss + 1e-8f);
                    #pragma unroll
                    for (int nt = 0; nt < 8; nt++) {
                        v[rr][nt][0] *= inv;
                        v[rr][nt][1] *= inv;
                    }
                }
            }
            const int h_ = (n0 >> 6) + wn;
            const int b_ = r0 >> 11;
            #pragma unroll
            for (int rr = 0; rr < 2; rr++) {
                const int s_ = (r0 + rr*8) & 2047;
                if (mode == 1) {
                    // V: fp16 single, transposed [b,h,d,s]
                    __half* Vf = (__half*)Yh;
                    const size_t base = (size_t)(b_ * NH + h_) * DK;
                    #pragma unroll
                    for (int nt = 0; nt < 8; nt++) {
                        int d = nt*8 + tig*2;
                        Vf[(base + d    ) * SEQ + s_] = __float2half(v[rr][nt][0]);
                        Vf[(base + d + 1) * SEQ + s_] = __float2half(v[rr][nt][1]);
                    }
                } else {
                    const size_t base = ((size_t)(b_ * NH + h_) * SEQ + s_) * DK;
                    #pragma unroll
                    for (int nt = 0; nt < 8; nt++) {
                        uint32_t hp, lp;
                        split2(v[rr][nt][0], v[rr][nt][1], hp, lp);
                        *(uint32_t*)(Yh + base + nt*8 + tig*2) = hp;
                        *(uint32_t*)(Yl + base + nt*8 + tig*2) = lp;
                    }
                }
            }
        }
    }
#undef G_LOAD
}

// ---------------------------------------------------------------------------
// Attention: CTA = (bh, 128-q tile), 8 warps x 16 q-rows, 64-key chunks,
// 2-stage cp.async, 1 sync/iter. S: bf16 3-term. PV: fp16 single x fp16 single.
// ---------------------------------------------------------------------------
#define A_QARR  16384                 /* 128 rows x 128B */
#define A_KARR  8192                  /* 64 rows x 128B */
#define A_STAGE (3*A_KARR)            /* 24576: Kh Kl Vf */
#define A_QTOT  (2*A_QARR)            /* 32768 */
#define ATTN_SMEM (A_QTOT + 2*A_STAGE)   /* 81920 */
__global__ void __launch_bounds__(256, 2) attn_mma(
    const __nv_bfloat16* __restrict__ qhp, const __nv_bfloat16* __restrict__ qlp,
    const __nv_bfloat16* __restrict__ khp, const __nv_bfloat16* __restrict__ klp,
    const __half* __restrict__ vfp,
    __nv_bfloat16* __restrict__ ch, __nv_bfloat16* __restrict__ cl)
{
    extern __shared__ char sm[];
    const uint32_t sb = smem_u32(sm);
    const int t = threadIdx.x, lane = t & 31, w = t >> 5;
    const int q0 = blockIdx.x * 128;
    const int bh = blockIdx.y;
    const size_t base = (size_t)bh * SEQ * DK;

    const __nv_bfloat16* Ksrc[2] = { khp + base, klp + base };
    const __half* Vsrc = vfp + base;

    const int krow = t >> 2, kch = t & 3;   // 64 rows; chunks kch and kch+4

#define A_LOADKV(kt, st) do { \
    _Pragma("unroll") \
    for (int p_ = 0; p_ < 2; p_++) { \
        uint32_t kb = sb + A_QTOT + (st)*A_STAGE + p_*A_KARR; \
        CP16(kb + SWK(krow, kch),     Ksrc[p_] + (size_t)((kt) + krow) * DK + kch*8); \
        CP16(kb + SWK(krow, kch + 4), Ksrc[p_] + (size_t)((kt) + krow) * DK + (kch + 4)*8); \
    } \
    uint32_t vb = sb + A_QTOT + (st)*A_STAGE + 2*A_KARR; \
    CP16(vb + SWK(krow, kch),     Vsrc + (size_t)krow * SEQ + (kt) + kch*8); \
    CP16(vb + SWK(krow, kch + 4), Vsrc + (size_t)krow * SEQ + (kt) + (kch + 4)*8); \
} while (0)

    // Q loads: 128 rows x 8 chunks per part
    {
        const __nv_bfloat16* Qsrc[2] = { qhp + base, qlp + base };
        #pragma unroll
        for (int p_ = 0; p_ < 2; p_++)
            #pragma unroll
            for (int i = 0; i < 4; i++) {
                int c = t + i*256, row = c >> 3, chn = c & 7;
                CP16(sb + p_*A_QARR + SWK(row, chn),
                     Qsrc[p_] + (size_t)(q0 + row) * DK + chn*8);
            }
    }
    A_LOADKV(0, 0);  CPC();

    const int aRow = w*16 + (lane & 15);
    const int aChH = lane >> 4;
    const int bRowOff = (lane & 7) + ((lane >> 4) << 3);
    const int bChH = (lane >> 3) & 1;

    float o[8][4];
    #pragma unroll
    for (int i = 0; i < 8; i++)
        #pragma unroll
        for (int j = 0; j < 4; j++) o[i][j] = 0.f;

    #pragma unroll 1
    for (int kc = 0; kc < 32; kc++) {
        const int st = kc & 1;
        CPW(0);
        __syncthreads();
        if (kc + 1 < 32) A_LOADKV((kc + 1) * 64, st ^ 1);
        CPC();

        const uint32_t uKh = sb + A_QTOT + st*A_STAGE;
        const uint32_t uKl = uKh + A_KARR;
        const uint32_t uVf = uKh + 2*A_KARR;

        // S = Qn Kn^T over 64 keys (bf16 3-term)
        float s[8][4];
        #pragma unroll
        for (int i = 0; i < 8; i++)
            #pragma unroll
            for (int j = 0; j < 4; j++) s[i][j] = 0.f;

        #pragma unroll
        for (int ks = 0; ks < 4; ks++) {
            uint32_t aQh[4], aQl[4];
            int qc = ks*2 + aChH;
            LDM4(aQh, sb + SWK(aRow, qc));
            LDM4(aQl, sb + A_QARR + SWK(aRow, qc));
            const int cb = ks*2 + bChH;
            #pragma unroll
            for (int nt2 = 0; nt2 < 4; nt2++) {
                int r = bRowOff + nt2*16;
                uint32_t rh[4], rl[4];
                LDM4(rh, uKh + SWK(r, cb));
                LDM4(rl, uKl + SWK(r, cb));
                uint32_t bh0[2] = {rh[0], rh[1]}, bh1[2] = {rh[2], rh[3]};
                uint32_t bl0[2] = {rl[0], rl[1]}, bl1[2] = {rl[2], rl[3]};
                const int nA = nt2*2, nB = nt2*2 + 1;
                MMA(s[nA], aQh, bh0); MMA(s[nB], aQh, bh1);
                MMA(s[nA], aQh, bl0); MMA(s[nB], aQh, bl1);
                MMA(s[nA], aQl, bh0); MMA(s[nB], aQl, bh1);
            }
        }

        // P = S^2 -> fp16 single, O += P V (fp16 x fp16, fp32 accum)
        #pragma unroll
        for (int kt2 = 0; kt2 < 4; kt2++) {
            uint32_t aP[4];
            aP[0] = pack_h2(s[2*kt2][0]*s[2*kt2][0],     s[2*kt2][1]*s[2*kt2][1]);
            aP[1] = pack_h2(s[2*kt2][2]*s[2*kt2][2],     s[2*kt2][3]*s[2*kt2][3]);
            aP[2] = pack_h2(s[2*kt2+1][0]*s[2*kt2+1][0], s[2*kt2+1][1]*s[2*kt2+1][1]);
            aP[3] = pack_h2(s[2*kt2+1][2]*s[2*kt2+1][2], s[2*kt2+1][3]*s[2*kt2+1][3]);
            const int cb = kt2*2 + bChH;
            #pragma unroll
            for (int nt2 = 0; nt2 < 4; nt2++) {
                int r = bRowOff + nt2*16;
                uint32_t rv[4];
                LDM4(rv, uVf + SWK(r, cb));
                uint32_t b0[2] = {rv[0], rv[1]}, b1[2] = {rv[2], rv[3]};
                MMAH(o[nt2*2], aP, b0);
                MMAH(o[nt2*2 + 1], aP, b1);
            }
        }
    }

    // ctx epilogue: split bf16, [b, s, DM]
    const int g = lane >> 2, tig = lane & 3;
    const int r0 = q0 + w*16 + g;
    const int b_ = bh >> 4, h_ = bh & 15;
    #pragma unroll
    for (int rr = 0; rr < 2; rr++) {
        const int s_ = r0 + rr*8;
        const size_t ob = ((size_t)b_ * SEQ + s_) * DM + h_ * DK;
        #pragma unroll
        for (int nt = 0; nt < 8; nt++) {
            uint32_t hp, lp;
            split2(o[nt][rr*2], o[nt][rr*2+1], hp, lp);
            *(uint32_t*)(ch + ob + nt*8 + tig*2) = hp;
            *(uint32_t*)(cl + ob + nt*8 + tig*2) = lp;
        }
    }
#undef A_LOADKV
}

// ---------------------------------------------------------------------------
extern "C" void kernel_launch(void* const* d_in, const int* in_sizes, int n_in,
                              void* d_out, int out_size)
{
    const float* Q    = (const float*)d_in[0];
    const float* K    = (const float*)d_in[1];
    const float* V    = (const float*)d_in[2];
    const float* Wq_w = (const float*)d_in[3];
    const float* Wq_b = (const float*)d_in[4];
    const float* Wk_w = (const float*)d_in[5];
    const float* Wk_b = (const float*)d_in[6];
    const float* Wv_w = (const float*)d_in[7];
    const float* Wv_b = (const float*)d_in[8];
    const float* Wo_w = (const float*)d_in[9];
    const float* Wo_b = (const float*)d_in[10];
    float* out = (float*)d_out;

    __nv_bfloat16* gb;
    cudaGetSymbolAddress((void**)&gb, g_buf);

    __nv_bfloat16* xh[3] = { gb + OFF_XQH, gb + OFF_XKH, gb + OFF_XVH };
    __nv_bfloat16* xl[3] = { gb + OFF_XQL, gb + OFF_XKL, gb + OFF_XVL };
    __nv_bfloat16* wh[4]; __nv_bfloat16* wl[4];
    for (int i = 0; i < 4; i++) { wh[i] = gb + OFF_W + (size_t)(2*i) * NW; wl[i] = wh[i] + NW; }
    __nv_bfloat16 *qh = gb + OFF_QH, *ql = gb + OFF_QL;
    __nv_bfloat16 *kh = gb + OFF_KH, *kl = gb + OFF_KL;
    __half        *vf = (__half*)(gb + OFF_VF);
    __nv_bfloat16 *ch = gb + OFF_CH, *cl = gb + OFF_CL;

    cudaFuncSetAttribute(gemm_mma, cudaFuncAttributeMaxDynamicSharedMemorySize, GEMM_SMEM);
    cudaFuncSetAttribute(attn_mma, cudaFuncAttributeMaxDynamicSharedMemorySize, ATTN_SMEM);

    SplitArgs ia;
    ia.s[0] = (const float4*)Q; ia.s[1] = (const float4*)K; ia.s[2] = (const float4*)V;
    ia.s[3] = (const float4*)Q;
    for (int i = 0; i < 3; i++) { ia.h[i] = (uint4*)xh[i]; ia.l[i] = (uint4*)xl[i]; }
    ia.h[3] = (uint4*)xh[0]; ia.l[3] = (uint4*)xl[0];
    split_multi<<<dim3(NX/8/256, 3), 256>>>(ia, NX/8);

    SplitArgs wa;
    wa.s[0] = (const float4*)Wq_w; wa.s[1] = (const float4*)Wk_w;
    wa.s[2] = (const float4*)Wv_w; wa.s[3] = (const float4*)Wo_w;
    for (int i = 0; i < 4; i++) { wa.h[i] = (uint4*)wh[i]; wa.l[i] = (uint4*)wl[i]; }
    split_multi<<<dim3(NW/8/256, 4), 256>>>(wa, NW/8);

    GemmArgs gqkv;
    gqkv.ah[0] = xh[0]; gqkv.al[0] = xl[0]; gqkv.wh[0] = wh[0]; gqkv.wl[0] = wl[0];
    gqkv.bias[0] = Wq_b; gqkv.yf[0] = nullptr; gqkv.yh[0] = qh; gqkv.yl[0] = ql; gqkv.mode[0] = 3;
    gqkv.ah[1] = xh[1]; gqkv.al[1] = xl[1]; gqkv.wh[1] = wh[1]; gqkv.wl[1] = wl[1];
    gqkv.bias[1] = Wk_b; gqkv.yf[1] = nullptr; gqkv.yh[1] = kh; gqkv.yl[1] = kl; gqkv.mode[1] = 3;
    gqkv.ah[2] = xh[2]; gqkv.al[2] = xl[2]; gqkv.wh[2] = wh[2]; gqkv.wl[2] = wl[2];
    gqkv.bias[2] = Wv_b; gqkv.yf[2] = nullptr; gqkv.yh[2] = (__nv_bfloat16*)vf;
    gqkv.yl[2] = nullptr; gqkv.mode[2] = 1;
    gemm_mma<<<dim3(DM/128, MTOT/256, 3), 256, GEMM_SMEM>>>(gqkv);

    dim3 agrid(SEQ/128, NBH);       // (16, 32) = 512 CTAs, 2/SM
    attn_mma<<<agrid, 256, ATTN_SMEM>>>(qh, ql, kh, kl, vf, ch, cl);

    GemmArgs go;
    go.ah[0] = ch; go.al[0] = cl; go.wh[0] = wh[3]; go.wl[0] = wl[3];
    go.bias[0] = Wo_b; go.yf[0] = out; go.yh[0] = nullptr; go.yl[0] = nullptr; go.mode[0] = 0;
    go.ah[1] = go.ah[0]; go.al[1] = go.al[0]; go.wh[1] = go.wh[0]; go.wl[1] = go.wl[0];
    go.bias[1] = go.bias[0]; go.yf[1] = go.yf[0]; go.yh[1] = nullptr; go.yl[1] = nullptr; go.mode[1] = 0;
    go.ah[2] = go.ah[0]; go.al[2] = go.al[0]; go.wh[2] = go.wh[0]; go.wl[2] = go.wl[0];
    go.bias[2] = go.bias[0]; go.yf[2] = go.yf[0]; go.yh[2] = nullptr; go.yl[2] = nullptr; go.mode[2] = 0;
    gemm_mma<<<dim3(DM/128, MTOT/256, 1), 256, GEMM_SMEM>>>(go);
}

// round 12
// speedup vs baseline: 1.5849x; 1.3155x over previous
#include <cuda_runtime.h>
#include <cuda_bf16.h>
#include <cuda_fp16.h>
#include <stdint.h>

#define DM 1024
#define NH 16
#define DK 64
#define SEQ 2048
#define MTOT 4096
#define NBH 32
#define NX (MTOT*DM)
#define NW (DM*DM)

// scratch arena (typed bf16, used as raw 2-byte storage)
__device__ __nv_bfloat16 g_buf[14ull*NX + 8ull*NW];

#define OFF_XQH 0ull
#define OFF_XQL (1ull*NX)
#define OFF_XKH (2ull*NX)
#define OFF_XKL (3ull*NX)
#define OFF_XVH (4ull*NX)
#define OFF_XVL (5ull*NX)
#define OFF_W   (6ull*NX)
#define OFF_QH  (OFF_W + 8ull*NW)
#define OFF_QL  (OFF_QH + 1ull*NX)
#define OFF_KF  (OFF_QH + 2ull*NX)   /* fp16 single */
#define OFF_VF  (OFF_QH + 4ull*NX)   /* fp16 single, transposed [b,h,d,s] */
#define OFF_CH  (OFF_QH + 6ull*NX)
#define OFF_CL  (OFF_QH + 7ull*NX)

static __device__ __forceinline__ uint32_t smem_u32(const void* p) {
    uint32_t a;
    asm("{ .reg .u64 t; cvta.to.shared.u64 t, %1; cvt.u32.u64 %0, t; }" : "=r"(a) : "l"(p));
    return a;
}

#define MMAH(C, A, B) asm volatile( \
    "mma.sync.aligned.m16n8k16.row.col.f32.f16.f16.f32 " \
    "{%0,%1,%2,%3}, {%4,%5,%6,%7}, {%8,%9}, {%0,%1,%2,%3};" \
    : "+f"((C)[0]), "+f"((C)[1]), "+f"((C)[2]), "+f"((C)[3]) \
    : "r"((A)[0]), "r"((A)[1]), "r"((A)[2]), "r"((A)[3]), \
      "r"((B)[0]), "r"((B)[1]))

#define LDM4(R, ADDR) asm volatile( \
    "ldmatrix.sync.aligned.m8n8.x4.shared.b16 {%0,%1,%2,%3}, [%4];" \
    : "=r"((R)[0]), "=r"((R)[1]), "=r"((R)[2]), "=r"((R)[3]) : "r"(ADDR))

#define CP16(d, s) asm volatile("cp.async.cg.shared.global [%0], [%1], 16;" :: "r"(d), "l"(s))
#define CPC()   asm volatile("cp.async.commit_group;")
#define CPW(n)  asm volatile("cp.async.wait_group %0;" :: "n"(n))

// swizzles (byte offsets). SWC: 64B rows (4x16B chunks). SWK: 128B rows (8x16B chunks).
#define SWC(row, ch) (((row) << 6) + ((((ch) ^ (((row) >> 1) & 3))) << 4))
#define SWK(row, ch) (((row) << 7) + ((((ch) ^ ((row) & 7))) << 4))

// fp16 hi+lo split of a pair
static __device__ __forceinline__ void split2h(float x0, float x1,
                                               uint32_t& hp, uint32_t& lp) {
    __half h0 = __float2half(x0), h1 = __float2half(x1);
    __half l0 = __float2half(x0 - __half2float(h0));
    __half l1 = __float2half(x1 - __half2float(h1));
    hp = (uint32_t)__half_as_ushort(h0) | ((uint32_t)__half_as_ushort(h1) << 16);
    lp = (uint32_t)__half_as_ushort(l0) | ((uint32_t)__half_as_ushort(l1) << 16);
}
static __device__ __forceinline__ uint32_t pack_h2(float x0, float x1) {
    __half2 h = __floats2half2_rn(x0, x1);
    return *(uint32_t*)&h;
}

// ---------------------------------------------------------------------------
// input split: fp32 -> fp16 hi + fp16 lo (3 tensors via grid.y)
struct SplitArgs {
    const float4* s[4];
    uint4* h[4];
    uint4* l[4];
};
__global__ void split_multi(SplitArgs a, int nchunks)
{
    const int y = blockIdx.y;
    const float4* src = a.s[y];
    uint4* hi = a.h[y];
    uint4* lo = a.l[y];
    int i = blockIdx.x * blockDim.x + threadIdx.x;
    if (i >= nchunks) return;
    float4 p = src[i*2], q = src[i*2+1];
    uint4 H, L;
    split2h(p.x, p.y, H.x, L.x);
    split2h(p.z, p.w, H.y, L.y);
    split2h(q.x, q.y, H.z, L.z);
    split2h(q.z, q.w, H.w, L.w);
    hi[i] = H;
    lo[i] = L;
}

// weight convert: fp32 -> fp16 single (4 tensors via grid.y)
struct ConvArgs {
    const float4* s[4];
    uint4* o[4];
};
__global__ void conv_half(ConvArgs a, int nchunks)
{
    const int y = blockIdx.y;
    const float4* src = a.s[y];
    uint4* dst = a.o[y];
    int i = blockIdx.x * blockDim.x + threadIdx.x;
    if (i >= nchunks) return;
    float4 p = src[i*2], q = src[i*2+1];
    uint4 O;
    O.x = pack_h2(p.x, p.y);
    O.y = pack_h2(p.z, p.w);
    O.z = pack_h2(q.x, q.y);
    O.w = pack_h2(q.z, q.w);
    dst[i] = O;
}

// ---------------------------------------------------------------------------
// Batched GEMM: Y = A @ W^T + bias. A = fp16 hi+lo split, W = fp16 single.
// CTA 256x128, k-step 64 (two 32-k sub-blocks), 2-stage, 1 sync/iter.
// mode 0: fp32 out. mode 1: V fp16 single transposed [b,h,d,s].
// mode 3: Q rownorm + fp16 split2 [b,h,s,d]. mode 4: K rownorm + fp16 single.
// ---------------------------------------------------------------------------
struct GemmArgs {
    const __half* ah[3];
    const __half* al[3];
    const __half* wf[3];
    const float* bias[3];
    float* yf[3];
    __half* yh[3];
    __half* yl[3];
    int mode[3];
};
#define G_SUB    40960    /* A hi 16K + A lo 16K + B 8K */
#define G_STAGE  81920
#define GEMM_SMEM (2*G_STAGE)   /* 163840 */
__global__ void __launch_bounds__(256, 1) gemm_mma(GemmArgs ga)
{
    extern __shared__ char sm[];
    const uint32_t sb = smem_u32(sm);
    const int z = blockIdx.z;
    const int t = threadIdx.x, lane = t & 31, w = t >> 5;
    const int wm = w & 3, wn = w >> 2;
    const int n0 = blockIdx.x * 128, m0 = blockIdx.y * 256;
    const int mode = ga.mode[z];
    const float* bias = ga.bias[z];

    const __half* aSrc[2] = { ga.ah[z] + (size_t)m0 * DM, ga.al[z] + (size_t)m0 * DM };
    const __half* bSrc = ga.wf[z] + (size_t)n0 * DM;

    const int lrow = t >> 2, lch = t & 3;

#define G_LOAD(kt, st) do { \
    _Pragma("unroll") \
    for (int s_2 = 0; s_2 < 2; s_2++) { \
        _Pragma("unroll") \
        for (int p_ = 0; p_ < 2; p_++) { \
            uint32_t ab = sb + (st)*G_STAGE + s_2*G_SUB + p_*16384; \
            _Pragma("unroll") \
            for (int j_ = 0; j_ < 4; j_++) { \
                int r_ = lrow + j_*64; \
                CP16(ab + SWC(r_, lch), aSrc[p_] + (size_t)r_ * DM + (kt) + s_2*32 + lch*8); \
            } \
        } \
        uint32_t bb = sb + (st)*G_STAGE + s_2*G_SUB + 32768; \
        _Pragma("unroll") \
        for (int j_ = 0; j_ < 2; j_++) { \
            int r_ = lrow + j_*64; \
            CP16(bb + SWC(r_, lch), bSrc + (size_t)r_ * DM + (kt) + s_2*32 + lch*8); \
        } \
    } \
} while (0)

    float acc[4][8][4];
    #pragma unroll
    for (int i = 0; i < 4; i++)
        #pragma unroll
        for (int j = 0; j < 8; j++)
            #pragma unroll
            for (int k = 0; k < 4; k++) acc[i][j][k] = 0.f;

    const int aRow0 = wm*64 + (lane & 15);
    const int aChH  = lane >> 4;
    const int bRowOff = wn*64 + (lane & 7) + ((lane >> 4) << 3);
    const int bChH  = (lane >> 3) & 1;

    G_LOAD(0, 0);  CPC();

    #pragma unroll 1
    for (int kc = 0; kc < 16; kc++) {
        const int st = kc & 1;
        CPW(0);
        __syncthreads();
        if (kc + 1 < 16) G_LOAD((kc + 1) * 64, st ^ 1);
        CPC();

        #pragma unroll
        for (int sub = 0; sub < 2; sub++) {
            const uint32_t uAh = sb + st*G_STAGE + sub*G_SUB;
            const uint32_t uAl = uAh + 16384;
            const uint32_t uBf = uAh + 32768;
            #pragma unroll
            for (int ks = 0; ks < 2; ks++) {
                const int c = ks*2 + aChH;
                uint32_t aF[2][4][4];
                #pragma unroll
                for (int mt = 0; mt < 4; mt++) {
                    LDM4(aF[0][mt], uAh + SWC(aRow0 + mt*16, c));
                    LDM4(aF[1][mt], uAl + SWC(aRow0 + mt*16, c));
                }
                const int cb = ks*2 + bChH;
                #pragma unroll
                for (int nt2 = 0; nt2 < 4; nt2++) {
                    int r = bRowOff + nt2*16;
                    uint32_t rv[4];
                    LDM4(rv, uBf + SWC(r, cb));
                    uint32_t b0[2] = {rv[0], rv[1]}, b1[2] = {rv[2], rv[3]};
                    const int nA = nt2*2, nB = nt2*2 + 1;
                    #pragma unroll
                    for (int mt = 0; mt < 4; mt++) {
                        MMAH(acc[mt][nA], aF[0][mt], b0);
                        MMAH(acc[mt][nB], aF[0][mt], b1);
                    }
                    #pragma unroll
                    for (int mt = 0; mt < 4; mt++) {
                        MMAH(acc[mt][nA], aF[1][mt], b0);
                        MMAH(acc[mt][nB], aF[1][mt], b1);
                    }
                }
            }
        }
    }

    // ---- epilogue ----
    float* Yf = ga.yf[z];
    __half* Yh = ga.yh[z];
    __half* Yl = ga.yl[z];
    const int g = lane >> 2, tig = lane & 3;
    #pragma unroll
    for (int mt = 0; mt < 4; mt++) {
        const int r0 = m0 + wm*64 + mt*16 + g;
        float v[2][8][2];
        #pragma unroll
        for (int nt = 0; nt < 8; nt++) {
            int col = n0 + wn*64 + nt*8 + tig*2;
            float b0v = bias[col], b1v = bias[col + 1];
            v[0][nt][0] = acc[mt][nt][0] + b0v;
            v[0][nt][1] = acc[mt][nt][1] + b1v;
            v[1][nt][0] = acc[mt][nt][2] + b0v;
            v[1][nt][1] = acc[mt][nt][3] + b1v;
        }
        if (mode == 0) {
            #pragma unroll
            for (int rr = 0; rr < 2; rr++) {
                int r = r0 + rr*8;
                #pragma unroll
                for (int nt = 0; nt < 8; nt++) {
                    int col = n0 + wn*64 + nt*8 + tig*2;
                    *(float2*)(Yf + (size_t)r * DM + col) =
                        make_float2(v[rr][nt][0], v[rr][nt][1]);
                }
            }
        } else {
            if (mode >= 3) {   // rownorm for Q (3) and K (4)
                #pragma unroll
                for (int rr = 0; rr < 2; rr++) {
                    float ss = 0.f;
                    #pragma unroll
                    for (int nt = 0; nt < 8; nt++)
                        ss += v[rr][nt][0]*v[rr][nt][0] + v[rr][nt][1]*v[rr][nt][1];
                    ss += __shfl_xor_sync(0xffffffffu, ss, 1);
                    ss += __shfl_xor_sync(0xffffffffu, ss, 2);
                    float inv = rsqrtf(ss + 1e-8f);
                    #pragma unroll
                    for (int nt = 0; nt < 8; nt++) {
                        v[rr][nt][0] *= inv;
                        v[rr][nt][1] *= inv;
                    }
                }
            }
            const int h_ = (n0 >> 6) + wn;
            const int b_ = r0 >> 11;
            #pragma unroll
            for (int rr = 0; rr < 2; rr++) {
                const int s_ = (r0 + rr*8) & 2047;
                if (mode == 1) {
                    // V: fp16 single, transposed [b,h,d,s]
                    const size_t base = (size_t)(b_ * NH + h_) * DK;
                    #pragma unroll
                    for (int nt = 0; nt < 8; nt++) {
                        int d = nt*8 + tig*2;
                        Yh[(base + d    ) * SEQ + s_] = __float2half(v[rr][nt][0]);
                        Yh[(base + d + 1) * SEQ + s_] = __float2half(v[rr][nt][1]);
                    }
                } else if (mode == 4) {
                    // K: fp16 single [b,h,s,d]
                    const size_t base = ((size_t)(b_ * NH + h_) * SEQ + s_) * DK;
                    #pragma unroll
                    for (int nt = 0; nt < 8; nt++)
                        *(uint32_t*)(Yh + base + nt*8 + tig*2) =
                            pack_h2(v[rr][nt][0], v[rr][nt][1]);
                } else {
                    // Q: fp16 split2 [b,h,s,d]
                    const size_t base = ((size_t)(b_ * NH + h_) * SEQ + s_) * DK;
                    #pragma unroll
                    for (int nt = 0; nt < 8; nt++) {
                        uint32_t hp, lp;
                        split2h(v[rr][nt][0], v[rr][nt][1], hp, lp);
                        *(uint32_t*)(Yh + base + nt*8 + tig*2) = hp;
                        *(uint32_t*)(Yl + base + nt*8 + tig*2) = lp;
                    }
                }
            }
        }
    }
#undef G_LOAD
}

// ---------------------------------------------------------------------------
// Attention: CTA = (bh, 128-q tile), 8 warps x 16 q-rows, 64-key chunks,
// 2-stage cp.async, 1 sync/iter.
// S: Q fp16 split-2 (A) x K fp16 single (B) = 4 MMAs/(ks,nt2).
// PV: P fp16 single x V fp16 single.
// ---------------------------------------------------------------------------
#define A_QARR  16384                 /* 128 rows x 128B */
#define A_KARR  8192                  /* 64 rows x 128B */
#define A_STAGE (2*A_KARR)            /* 16384: Kf Vf */
#define A_QTOT  (2*A_QARR)            /* 32768 */
#define ATTN_SMEM (A_QTOT + 2*A_STAGE)   /* 65536 */
__global__ void __launch_bounds__(256, 2) attn_mma(
    const __half* __restrict__ qhp, const __half* __restrict__ qlp,
    const __half* __restrict__ kfp, const __half* __restrict__ vfp,
    __half* __restrict__ ch, __half* __restrict__ cl)
{
    extern __shared__ char sm[];
    const uint32_t sb = smem_u32(sm);
    const int t = threadIdx.x, lane = t & 31, w = t >> 5;
    const int q0 = blockIdx.x * 128;
    const int bh = blockIdx.y;
    const size_t base = (size_t)bh * SEQ * DK;

    const __half* Ksrc = kfp + base;
    const __half* Vsrc = vfp + base;

    const int krow = t >> 2, kch = t & 3;

#define A_LOADKV(kt, st) do { \
    uint32_t kb = sb + A_QTOT + (st)*A_STAGE; \
    CP16(kb + SWK(krow, kch),     Ksrc + (size_t)((kt) + krow) * DK + kch*8); \
    CP16(kb + SWK(krow, kch + 4), Ksrc + (size_t)((kt) + krow) * DK + (kch + 4)*8); \
    uint32_t vb = kb + A_KARR; \
    CP16(vb + SWK(krow, kch),     Vsrc + (size_t)krow * SEQ + (kt) + kch*8); \
    CP16(vb + SWK(krow, kch + 4), Vsrc + (size_t)krow * SEQ + (kt) + (kch + 4)*8); \
} while (0)

    // Q loads: 128 rows x 8 chunks per part (hi, lo)
    {
        const __half* Qsrc[2] = { qhp + base, qlp + base };
        #pragma unroll
        for (int p_ = 0; p_ < 2; p_++)
            #pragma unroll
            for (int i = 0; i < 4; i++) {
                int c = t + i*256, row = c >> 3, chn = c & 7;
                CP16(sb + p_*A_QARR + SWK(row, chn),
                     Qsrc[p_] + (size_t)(q0 + row) * DK + chn*8);
            }
    }
    A_LOADKV(0, 0);  CPC();

    const int aRow = w*16 + (lane & 15);
    const int aChH = lane >> 4;
    const int bRowOff = (lane & 7) + ((lane >> 4) << 3);
    const int bChH = (lane >> 3) & 1;

    float o[8][4];
    #pragma unroll
    for (int i = 0; i < 8; i++)
        #pragma unroll
        for (int j = 0; j < 4; j++) o[i][j] = 0.f;

    #pragma unroll 1
    for (int kc = 0; kc < 32; kc++) {
        const int st = kc & 1;
        CPW(0);
        __syncthreads();
        if (kc + 1 < 32) A_LOADKV((kc + 1) * 64, st ^ 1);
        CPC();

        const uint32_t uKf = sb + A_QTOT + st*A_STAGE;
        const uint32_t uVf = uKf + A_KARR;

        // S = Qn Kn^T over 64 keys (Q split-2, K single)
        float s[8][4];
        #pragma unroll
        for (int i = 0; i < 8; i++)
            #pragma unroll
            for (int j = 0; j < 4; j++) s[i][j] = 0.f;

        #pragma unroll
        for (int ks = 0; ks < 4; ks++) {
            uint32_t aQh[4], aQl[4];
            int qc = ks*2 + aChH;
            LDM4(aQh, sb + SWK(aRow, qc));
            LDM4(aQl, sb + A_QARR + SWK(aRow, qc));
            const int cb = ks*2 + bChH;
            #pragma unroll
            for (int nt2 = 0; nt2 < 4; nt2++) {
                int r = bRowOff + nt2*16;
                uint32_t rk[4];
                LDM4(rk, uKf + SWK(r, cb));
                uint32_t b0[2] = {rk[0], rk[1]}, b1[2] = {rk[2], rk[3]};
                const int nA = nt2*2, nB = nt2*2 + 1;
                MMAH(s[nA], aQh, b0); MMAH(s[nB], aQh, b1);
                MMAH(s[nA], aQl, b0); MMAH(s[nB], aQl, b1);
            }
        }

        // P = S^2 -> fp16 single, O += P V
        #pragma unroll
        for (int kt2 = 0; kt2 < 4; kt2++) {
            uint32_t aP[4];
            aP[0] = pack_h2(s[2*kt2][0]*s[2*kt2][0],     s[2*kt2][1]*s[2*kt2][1]);
            aP[1] = pack_h2(s[2*kt2][2]*s[2*kt2][2],     s[2*kt2][3]*s[2*kt2][3]);
            aP[2] = pack_h2(s[2*kt2+1][0]*s[2*kt2+1][0], s[2*kt2+1][1]*s[2*kt2+1][1]);
            aP[3] = pack_h2(s[2*kt2+1][2]*s[2*kt2+1][2], s[2*kt2+1][3]*s[2*kt2+1][3]);
            const int cb = kt2*2 + bChH;
            #pragma unroll
            for (int nt2 = 0; nt2 < 4; nt2++) {
                int r = bRowOff + nt2*16;
                uint32_t rv[4];
                LDM4(rv, uVf + SWK(r, cb));
                uint32_t b0[2] = {rv[0], rv[1]}, b1[2] = {rv[2], rv[3]};
                MMAH(o[nt2*2], aP, b0);
                MMAH(o[nt2*2 + 1], aP, b1);
            }
        }
    }

    // ctx epilogue: fp16 split2, [b, s, DM]
    const int g = lane >> 2, tig = lane & 3;
    const int r0 = q0 + w*16 + g;
    const int b_ = bh >> 4, h_ = bh & 15;
    #pragma unroll
    for (int rr = 0; rr < 2; rr++) {
        const int s_ = r0 + rr*8;
        const size_t ob = ((size_t)b_ * SEQ + s_) * DM + h_ * DK;
        #pragma unroll
        for (int nt = 0; nt < 8; nt++) {
            uint32_t hp, lp;
            split2h(o[nt][rr*2], o[nt][rr*2+1], hp, lp);
            *(uint32_t*)(ch + ob + nt*8 + tig*2) = hp;
            *(uint32_t*)(cl + ob + nt*8 + tig*2) = lp;
        }
    }
#undef A_LOADKV
}

// ---------------------------------------------------------------------------
extern "C" void kernel_launch(void* const* d_in, const int* in_sizes, int n_in,
                              void* d_out, int out_size)
{
    const float* Q    = (const float*)d_in[0];
    const float* K    = (const float*)d_in[1];
    const float* V    = (const float*)d_in[2];
    const float* Wq_w = (const float*)d_in[3];
    const float* Wq_b = (const float*)d_in[4];
    const float* Wk_w = (const float*)d_in[5];
    const float* Wk_b = (const float*)d_in[6];
    const float* Wv_w = (const float*)d_in[7];
    const float* Wv_b = (const float*)d_in[8];
    const float* Wo_w = (const float*)d_in[9];
    const float* Wo_b = (const float*)d_in[10];
    float* out = (float*)d_out;

    __nv_bfloat16* gb;
    cudaGetSymbolAddress((void**)&gb, g_buf);

    __half* xh[3] = { (__half*)(gb + OFF_XQH), (__half*)(gb + OFF_XKH), (__half*)(gb + OFF_XVH) };
    __half* xl[3] = { (__half*)(gb + OFF_XQL), (__half*)(gb + OFF_XKL), (__half*)(gb + OFF_XVL) };
    __half* wf[4];
    for (int i = 0; i < 4; i++) wf[i] = (__half*)(gb + OFF_W) + (size_t)i * NW;
    __half *qh = (__half*)(gb + OFF_QH), *ql = (__half*)(gb + OFF_QL);
    __half *kf = (__half*)(gb + OFF_KF);
    __half *vf = (__half*)(gb + OFF_VF);
    __half *ch = (__half*)(gb + OFF_CH), *cl = (__half*)(gb + OFF_CL);

    cudaFuncSetAttribute(gemm_mma, cudaFuncAttributeMaxDynamicSharedMemorySize, GEMM_SMEM);
    cudaFuncSetAttribute(attn_mma, cudaFuncAttributeMaxDynamicSharedMemorySize, ATTN_SMEM);

    SplitArgs ia;
    ia.s[0] = (const float4*)Q; ia.s[1] = (const float4*)K; ia.s[2] = (const float4*)V;
    ia.s[3] = (const float4*)Q;
    for (int i = 0; i < 3; i++) { ia.h[i] = (uint4*)xh[i]; ia.l[i] = (uint4*)xl[i]; }
    ia.h[3] = (uint4*)xh[0]; ia.l[3] = (uint4*)xl[0];
    split_multi<<<dim3(NX/8/256, 3), 256>>>(ia, NX/8);

    ConvArgs wa;
    wa.s[0] = (const float4*)Wq_w; wa.s[1] = (const float4*)Wk_w;
    wa.s[2] = (const float4*)Wv_w; wa.s[3] = (const float4*)Wo_w;
    for (int i = 0; i < 4; i++) wa.o[i] = (uint4*)wf[i];
    conv_half<<<dim3(NW/8/256, 4), 256>>>(wa, NW/8);

    GemmArgs gqkv;
    gqkv.ah[0] = xh[0]; gqkv.al[0] = xl[0]; gqkv.wf[0] = wf[0];
    gqkv.bias[0] = Wq_b; gqkv.yf[0] = nullptr; gqkv.yh[0] = qh; gqkv.yl[0] = ql; gqkv.mode[0] = 3;
    gqkv.ah[1] = xh[1]; gqkv.al[1] = xl[1]; gqkv.wf[1] = wf[1];
    gqkv.bias[1] = Wk_b; gqkv.yf[1] = nullptr; gqkv.yh[1] = kf; gqkv.yl[1] = nullptr; gqkv.mode[1] = 4;
    gqkv.ah[2] = xh[2]; gqkv.al[2] = xl[2]; gqkv.wf[2] = wf[2];
    gqkv.bias[2] = Wv_b; gqkv.yf[2] = nullptr; gqkv.yh[2] = vf; gqkv.yl[2] = nullptr; gqkv.mode[2] = 1;
    gemm_mma<<<dim3(DM/128, MTOT/256, 3), 256, GEMM_SMEM>>>(gqkv);

    dim3 agrid(SEQ/128, NBH);       // (16, 32) = 512 CTAs, 2/SM
    attn_mma<<<agrid, 256, ATTN_SMEM>>>(qh, ql, kf, vf, ch, cl);

    GemmArgs go;
    go.ah[0] = ch; go.al[0] = cl; go.wf[0] = wf[3];
    go.bias[0] = Wo_b; go.yf[0] = out; go.yh[0] = nullptr; go.yl[0] = nullptr; go.mode[0] = 0;
    go.ah[1] = go.ah[0]; go.al[1] = go.al[0]; go.wf[1] = go.wf[0];
    go.bias[1] = go.bias[0]; go.yf[1] = go.yf[0]; go.yh[1] = nullptr; go.yl[1] = nullptr; go.mode[1] = 0;
    go.ah[2] = go.ah[0]; go.al[2] = go.al[0]; go.wf[2] = go.wf[0];
    go.bias[2] = go.bias[0]; go.yf[2] = go.yf[0]; go.yh[2] = nullptr; go.yl[2] = nullptr; go.mode[2] = 0;
    gemm_mma<<<dim3(DM/128, MTOT/256, 1), 256, GEMM_SMEM>>>(go);
}

// round 13
// speedup vs baseline: 2.0209x; 1.2751x over previous
#include <cuda_runtime.h>
#include <cuda_bf16.h>
#include <cuda_fp16.h>
#include <stdint.h>

#define DM 1024
#define NH 16
#define DK 64
#define SEQ 2048
#define MTOT 4096
#define NBH 32
#define NX (MTOT*DM)
#define NW (DM*DM)

// scratch arena (raw 2-byte storage)
__device__ __nv_bfloat16 g_buf[14ull*NX + 8ull*NW];

#define OFF_XQ  0ull                 /* fp16 single inputs */
#define OFF_XK  (1ull*NX)
#define OFF_XV  (2ull*NX)
#define OFF_W   (6ull*NX)
#define OFF_QH  (OFF_W + 8ull*NW)
#define OFF_QL  (OFF_QH + 1ull*NX)
#define OFF_KF  (OFF_QH + 2ull*NX)   /* fp16 single */
#define OFF_VF  (OFF_QH + 4ull*NX)   /* fp16 single, transposed [b,h,d,s] */
#define OFF_CH  (OFF_QH + 6ull*NX)
#define OFF_CL  (OFF_QH + 7ull*NX)

static __device__ __forceinline__ uint32_t smem_u32(const void* p) {
    uint32_t a;
    asm("{ .reg .u64 t; cvta.to.shared.u64 t, %1; cvt.u32.u64 %0, t; }" : "=r"(a) : "l"(p));
    return a;
}

#define MMAH(C, A, B) asm volatile( \
    "mma.sync.aligned.m16n8k16.row.col.f32.f16.f16.f32 " \
    "{%0,%1,%2,%3}, {%4,%5,%6,%7}, {%8,%9}, {%0,%1,%2,%3};" \
    : "+f"((C)[0]), "+f"((C)[1]), "+f"((C)[2]), "+f"((C)[3]) \
    : "r"((A)[0]), "r"((A)[1]), "r"((A)[2]), "r"((A)[3]), \
      "r"((B)[0]), "r"((B)[1]))

#define LDM4(R, ADDR) asm volatile( \
    "ldmatrix.sync.aligned.m8n8.x4.shared.b16 {%0,%1,%2,%3}, [%4];" \
    : "=r"((R)[0]), "=r"((R)[1]), "=r"((R)[2]), "=r"((R)[3]) : "r"(ADDR))

#define CP16(d, s) asm volatile("cp.async.cg.shared.global [%0], [%1], 16;" :: "r"(d), "l"(s))
#define CPC()   asm volatile("cp.async.commit_group;")
#define CPW(n)  asm volatile("cp.async.wait_group %0;" :: "n"(n))

// swizzles (byte offsets). SWC: 64B rows (4x16B chunks). SWK: 128B rows (8x16B chunks).
#define SWC(row, ch) (((row) << 6) + ((((ch) ^ (((row) >> 1) & 3))) << 4))
#define SWK(row, ch) (((row) << 7) + ((((ch) ^ ((row) & 7))) << 4))

static __device__ __forceinline__ void split2h(float x0, float x1,
                                               uint32_t& hp, uint32_t& lp) {
    __half h0 = __float2half(x0), h1 = __float2half(x1);
    __half l0 = __float2half(x0 - __half2float(h0));
    __half l1 = __float2half(x1 - __half2float(h1));
    hp = (uint32_t)__half_as_ushort(h0) | ((uint32_t)__half_as_ushort(h1) << 16);
    lp = (uint32_t)__half_as_ushort(l0) | ((uint32_t)__half_as_ushort(l1) << 16);
}
static __device__ __forceinline__ uint32_t pack_h2(float x0, float x1) {
    __half2 h = __floats2half2_rn(x0, x1);
    return *(uint32_t*)&h;
}

// ---------------------------------------------------------------------------
// unified fp32 -> fp16 single conversion for up to 7 tensors (grid.y selects)
struct ConvArgs {
    const float4* s[7];
    uint4* o[7];
    int nch[7];
};
__global__ void conv_multi(ConvArgs a)
{
    const int y = blockIdx.y;
    int i = blockIdx.x * blockDim.x + threadIdx.x;
    if (i >= a.nch[y]) return;
    const float4* src = a.s[y];
    float4 p = src[i*2], q = src[i*2+1];
    uint4 O;
    O.x = pack_h2(p.x, p.y);
    O.y = pack_h2(p.z, p.w);
    O.z = pack_h2(q.x, q.y);
    O.w = pack_h2(q.z, q.w);
    a.o[y][i] = O;
}

// ---------------------------------------------------------------------------
// Batched GEMM: Y = A @ W^T + bias. W = fp16 single.
// ASPLIT=1: A = fp16 hi+lo (2 MMAs). ASPLIT=0: A = fp16 single (1 MMA).
// CTA 256x128, k-step 64 (two 32-k sub-blocks), 2-stage, 1 sync/iter.
// mode 0: fp32 out. mode 1: V fp16 single transposed [b,h,d,s].
// mode 3: Q rownorm + fp16 split2 [b,h,s,d]. mode 4: K rownorm + fp16 single.
// ---------------------------------------------------------------------------
struct GemmArgs {
    const __half* ah[3];
    const __half* al[3];
    const __half* wf[3];
    const float* bias[3];
    float* yf[3];
    __half* yh[3];
    __half* yl[3];
    int mode[3];
};
#define G_SUB    40960    /* A hi 16K + A lo 16K + B 8K */
#define G_STAGE  81920
#define GEMM_SMEM (2*G_STAGE)   /* 163840 */
template<int ASPLIT>
__global__ void __launch_bounds__(256, 1) gemm_mma(GemmArgs ga)
{
    extern __shared__ char sm[];
    const uint32_t sb = smem_u32(sm);
    const int z = blockIdx.z;
    const int t = threadIdx.x, lane = t & 31, w = t >> 5;
    const int wm = w & 3, wn = w >> 2;
    const int n0 = blockIdx.x * 128, m0 = blockIdx.y * 256;
    const int mode = ga.mode[z];
    const float* bias = ga.bias[z];

    const __half* aSrc[2] = { ga.ah[z] + (size_t)m0 * DM,
                              ASPLIT ? ga.al[z] + (size_t)m0 * DM : ga.ah[z] };
    const __half* bSrc = ga.wf[z] + (size_t)n0 * DM;

    const int lrow = t >> 2, lch = t & 3;

#define G_LOAD(kt, st) do { \
    _Pragma("unroll") \
    for (int s_2 = 0; s_2 < 2; s_2++) { \
        _Pragma("unroll") \
        for (int p_ = 0; p_ < 1 + ASPLIT; p_++) { \
            uint32_t ab = sb + (st)*G_STAGE + s_2*G_SUB + p_*16384; \
            _Pragma("unroll") \
            for (int j_ = 0; j_ < 4; j_++) { \
                int r_ = lrow + j_*64; \
                CP16(ab + SWC(r_, lch), aSrc[p_] + (size_t)r_ * DM + (kt) + s_2*32 + lch*8); \
            } \
        } \
        uint32_t bb = sb + (st)*G_STAGE + s_2*G_SUB + 32768; \
        _Pragma("unroll") \
        for (int j_ = 0; j_ < 2; j_++) { \
            int r_ = lrow + j_*64; \
            CP16(bb + SWC(r_, lch), bSrc + (size_t)r_ * DM + (kt) + s_2*32 + lch*8); \
        } \
    } \
} while (0)

    float acc[4][8][4];
    #pragma unroll
    for (int i = 0; i < 4; i++)
        #pragma unroll
        for (int j = 0; j < 8; j++)
            #pragma unroll
            for (int k = 0; k < 4; k++) acc[i][j][k] = 0.f;

    const int aRow0 = wm*64 + (lane & 15);
    const int aChH  = lane >> 4;
    const int bRowOff = wn*64 + (lane & 7) + ((lane >> 4) << 3);
    const int bChH  = (lane >> 3) & 1;

    G_LOAD(0, 0);  CPC();

    #pragma unroll 1
    for (int kc = 0; kc < 16; kc++) {
        const int st = kc & 1;
        CPW(0);
        __syncthreads();
        if (kc + 1 < 16) G_LOAD((kc + 1) * 64, st ^ 1);
        CPC();

        #pragma unroll
        for (int sub = 0; sub < 2; sub++) {
            const uint32_t uAh = sb + st*G_STAGE + sub*G_SUB;
            const uint32_t uAl = uAh + 16384;
            const uint32_t uBf = uAh + 32768;
            #pragma unroll
            for (int ks = 0; ks < 2; ks++) {
                const int c = ks*2 + aChH;
                uint32_t aF[2][4][4];
                #pragma unroll
                for (int mt = 0; mt < 4; mt++) {
                    LDM4(aF[0][mt], uAh + SWC(aRow0 + mt*16, c));
                    if (ASPLIT) LDM4(aF[1][mt], uAl + SWC(aRow0 + mt*16, c));
                }
                const int cb = ks*2 + bChH;
                #pragma unroll
                for (int nt2 = 0; nt2 < 4; nt2++) {
                    int r = bRowOff + nt2*16;
                    uint32_t rv[4];
                    LDM4(rv, uBf + SWC(r, cb));
                    uint32_t b0[2] = {rv[0], rv[1]}, b1[2] = {rv[2], rv[3]};
                    const int nA = nt2*2, nB = nt2*2 + 1;
                    #pragma unroll
                    for (int mt = 0; mt < 4; mt++) {
                        MMAH(acc[mt][nA], aF[0][mt], b0);
                        MMAH(acc[mt][nB], aF[0][mt], b1);
                    }
                    if (ASPLIT) {
                        #pragma unroll
                        for (int mt = 0; mt < 4; mt++) {
                            MMAH(acc[mt][nA], aF[1][mt], b0);
                            MMAH(acc[mt][nB], aF[1][mt], b1);
                        }
                    }
                }
            }
        }
    }

    // ---- epilogue ----
    float* Yf = ga.yf[z];
    __half* Yh = ga.yh[z];
    __half* Yl = ga.yl[z];
    const int g = lane >> 2, tig = lane & 3;
    #pragma unroll
    for (int mt = 0; mt < 4; mt++) {
        const int r0 = m0 + wm*64 + mt*16 + g;
        float v[2][8][2];
        #pragma unroll
        for (int nt = 0; nt < 8; nt++) {
            int col = n0 + wn*64 + nt*8 + tig*2;
            float b0v = bias[col], b1v = bias[col + 1];
            v[0][nt][0] = acc[mt][nt][0] + b0v;
            v[0][nt][1] = acc[mt][nt][1] + b1v;
            v[1][nt][0] = acc[mt][nt][2] + b0v;
            v[1][nt][1] = acc[mt][nt][3] + b1v;
        }
        if (mode == 0) {
            #pragma unroll
            for (int rr = 0; rr < 2; rr++) {
                int r = r0 + rr*8;
                #pragma unroll
                for (int nt = 0; nt < 8; nt++) {
                    int col = n0 + wn*64 + nt*8 + tig*2;
                    *(float2*)(Yf + (size_t)r * DM + col) =
                        make_float2(v[rr][nt][0], v[rr][nt][1]);
                }
            }
        } else {
            if (mode >= 3) {   // rownorm for Q (3) and K (4)
                #pragma unroll
                for (int rr = 0; rr < 2; rr++) {
                    float ss = 0.f;
                    #pragma unroll
                    for (int nt = 0; nt < 8; nt++)
                        ss += v[rr][nt][0]*v[rr][nt][0] + v[rr][nt][1]*v[rr][nt][1];
                    ss += __shfl_xor_sync(0xffffffffu, ss, 1);
                    ss += __shfl_xor_sync(0xffffffffu, ss, 2);
                    float inv = rsqrtf(ss + 1e-8f);
                    #pragma unroll
                    for (int nt = 0; nt < 8; nt++) {
                        v[rr][nt][0] *= inv;
                        v[rr][nt][1] *= inv;
                    }
                }
            }
            const int h_ = (n0 >> 6) + wn;
            const int b_ = r0 >> 11;
            #pragma unroll
            for (int rr = 0; rr < 2; rr++) {
                const int s_ = (r0 + rr*8) & 2047;
                if (mode == 1) {
                    const size_t base = (size_t)(b_ * NH + h_) * DK;
                    #pragma unroll
                    for (int nt = 0; nt < 8; nt++) {
                        int d = nt*8 + tig*2;
                        Yh[(base + d    ) * SEQ + s_] = __float2half(v[rr][nt][0]);
                        Yh[(base + d + 1) * SEQ + s_] = __float2half(v[rr][nt][1]);
                    }
                } else if (mode == 4) {
                    const size_t base = ((size_t)(b_ * NH + h_) * SEQ + s_) * DK;
                    #pragma unroll
                    for (int nt = 0; nt < 8; nt++)
                        *(uint32_t*)(Yh + base + nt*8 + tig*2) =
                            pack_h2(v[rr][nt][0], v[rr][nt][1]);
                } else {
                    const size_t base = ((size_t)(b_ * NH + h_) * SEQ + s_) * DK;
                    #pragma unroll
                    for (int nt = 0; nt < 8; nt++) {
                        uint32_t hp, lp;
                        split2h(v[rr][nt][0], v[rr][nt][1], hp, lp);
                        *(uint32_t*)(Yh + base + nt*8 + tig*2) = hp;
                        *(uint32_t*)(Yl + base + nt*8 + tig*2) = lp;
                    }
                }
            }
        }
    }
#undef G_LOAD
}

// ---------------------------------------------------------------------------
// Attention: CTA = (bh, 128-q tile), 8 warps x 16 q-rows, 64-key chunks,
// 2-stage cp.async, 1 sync/iter.
// S: Q fp16 split-2 x K fp16 single. PV: P fp16 x V fp16.
// ---------------------------------------------------------------------------
#define A_QARR  16384
#define A_KARR  8192
#define A_STAGE (2*A_KARR)
#define A_QTOT  (2*A_QARR)
#define ATTN_SMEM (A_QTOT + 2*A_STAGE)   /* 65536 */
__global__ void __launch_bounds__(256, 2) attn_mma(
    const __half* __restrict__ qhp, const __half* __restrict__ qlp,
    const __half* __restrict__ kfp, const __half* __restrict__ vfp,
    __half* __restrict__ ch, __half* __restrict__ cl)
{
    extern __shared__ char sm[];
    const uint32_t sb = smem_u32(sm);
    const int t = threadIdx.x, lane = t & 31, w = t >> 5;
    const int q0 = blockIdx.x * 128;
    const int bh = blockIdx.y;
    const size_t base = (size_t)bh * SEQ * DK;

    const __half* Ksrc = kfp + base;
    const __half* Vsrc = vfp + base;

    const int krow = t >> 2, kch = t & 3;

#define A_LOADKV(kt, st) do { \
    uint32_t kb = sb + A_QTOT + (st)*A_STAGE; \
    CP16(kb + SWK(krow, kch),     Ksrc + (size_t)((kt) + krow) * DK + kch*8); \
    CP16(kb + SWK(krow, kch + 4), Ksrc + (size_t)((kt) + krow) * DK + (kch + 4)*8); \
    uint32_t vb = kb + A_KARR; \
    CP16(vb + SWK(krow, kch),     Vsrc + (size_t)krow * SEQ + (kt) + kch*8); \
    CP16(vb + SWK(krow, kch + 4), Vsrc + (size_t)krow * SEQ + (kt) + (kch + 4)*8); \
} while (0)

    {
        const __half* Qsrc[2] = { qhp + base, qlp + base };
        #pragma unroll
        for (int p_ = 0; p_ < 2; p_++)
            #pragma unroll
            for (int i = 0; i < 4; i++) {
                int c = t + i*256, row = c >> 3, chn = c & 7;
                CP16(sb + p_*A_QARR + SWK(row, chn),
                     Qsrc[p_] + (size_t)(q0 + row) * DK + chn*8);
            }
    }
    A_LOADKV(0, 0);  CPC();

    const int aRow = w*16 + (lane & 15);
    const int aChH = lane >> 4;
    const int bRowOff = (lane & 7) + ((lane >> 4) << 3);
    const int bChH = (lane >> 3) & 1;

    float o[8][4];
    #pragma unroll
    for (int i = 0; i < 8; i++)
        #pragma unroll
        for (int j = 0; j < 4; j++) o[i][j] = 0.f;

    #pragma unroll 1
    for (int kc = 0; kc < 32; kc++) {
        const int st = kc & 1;
        CPW(0);
        __syncthreads();
        if (kc + 1 < 32) A_LOADKV((kc + 1) * 64, st ^ 1);
        CPC();

        const uint32_t uKf = sb + A_QTOT + st*A_STAGE;
        const uint32_t uVf = uKf + A_KARR;

        float s[8][4];
        #pragma unroll
        for (int i = 0; i < 8; i++)
            #pragma unroll
            for (int j = 0; j < 4; j++) s[i][j] = 0.f;

        #pragma unroll
        for (int ks = 0; ks < 4; ks++) {
            uint32_t aQh[4], aQl[4];
            int qc = ks*2 + aChH;
            LDM4(aQh, sb + SWK(aRow, qc));
            LDM4(aQl, sb + A_QARR + SWK(aRow, qc));
            const int cb = ks*2 + bChH;
            #pragma unroll
            for (int nt2 = 0; nt2 < 4; nt2++) {
                int r = bRowOff + nt2*16;
                uint32_t rk[4];
                LDM4(rk, uKf + SWK(r, cb));
                uint32_t b0[2] = {rk[0], rk[1]}, b1[2] = {rk[2], rk[3]};
                const int nA = nt2*2, nB = nt2*2 + 1;
                MMAH(s[nA], aQh, b0); MMAH(s[nB], aQh, b1);
                MMAH(s[nA], aQl, b0); MMAH(s[nB], aQl, b1);
            }
        }

        #pragma unroll
        for (int kt2 = 0; kt2 < 4; kt2++) {
            uint32_t aP[4];
            aP[0] = pack_h2(s[2*kt2][0]*s[2*kt2][0],     s[2*kt2][1]*s[2*kt2][1]);
            aP[1] = pack_h2(s[2*kt2][2]*s[2*kt2][2],     s[2*kt2][3]*s[2*kt2][3]);
            aP[2] = pack_h2(s[2*kt2+1][0]*s[2*kt2+1][0], s[2*kt2+1][1]*s[2*kt2+1][1]);
            aP[3] = pack_h2(s[2*kt2+1][2]*s[2*kt2+1][2], s[2*kt2+1][3]*s[2*kt2+1][3]);
            const int cb = kt2*2 + bChH;
            #pragma unroll
            for (int nt2 = 0; nt2 < 4; nt2++) {
                int r = bRowOff + nt2*16;
                uint32_t rv[4];
                LDM4(rv, uVf + SWK(r, cb));
                uint32_t b0[2] = {rv[0], rv[1]}, b1[2] = {rv[2], rv[3]};
                MMAH(o[nt2*2], aP, b0);
                MMAH(o[nt2*2 + 1], aP, b1);
            }
        }
    }

    // ctx epilogue: fp16 split2, [b, s, DM]
    const int g = lane >> 2, tig = lane & 3;
    const int r0 = q0 + w*16 + g;
    const int b_ = bh >> 4, h_ = bh & 15;
    #pragma unroll
    for (int rr = 0; rr < 2; rr++) {
        const int s_ = r0 + rr*8;
        const size_t ob = ((size_t)b_ * SEQ + s_) * DM + h_ * DK;
        #pragma unroll
        for (int nt = 0; nt < 8; nt++) {
            uint32_t hp, lp;
            split2h(o[nt][rr*2], o[nt][rr*2+1], hp, lp);
            *(uint32_t*)(ch + ob + nt*8 + tig*2) = hp;
            *(uint32_t*)(cl + ob + nt*8 + tig*2) = lp;
        }
    }
#undef A_LOADKV
}

// ---------------------------------------------------------------------------
extern "C" void kernel_launch(void* const* d_in, const int* in_sizes, int n_in,
                              void* d_out, int out_size)
{
    const float* Q    = (const float*)d_in[0];
    const float* K    = (const float*)d_in[1];
    const float* V    = (const float*)d_in[2];
    const float* Wq_w = (const float*)d_in[3];
    const float* Wq_b = (const float*)d_in[4];
    const float* Wk_w = (const float*)d_in[5];
    const float* Wk_b = (const float*)d_in[6];
    const float* Wv_w = (const float*)d_in[7];
    const float* Wv_b = (const float*)d_in[8];
    const float* Wo_w = (const float*)d_in[9];
    const float* Wo_b = (const float*)d_in[10];
    float* out = (float*)d_out;

    __nv_bfloat16* gb;
    cudaGetSymbolAddress((void**)&gb, g_buf);

    __half* xf[3] = { (__half*)(gb + OFF_XQ), (__half*)(gb + OFF_XK), (__half*)(gb + OFF_XV) };
    __half* wf[4];
    for (int i = 0; i < 4; i++) wf[i] = (__half*)(gb + OFF_W) + (size_t)i * NW;
    __half *qh = (__half*)(gb + OFF_QH), *ql = (__half*)(gb + OFF_QL);
    __half *kf = (__half*)(gb + OFF_KF);
    __half *vf = (__half*)(gb + OFF_VF);
    __half *ch = (__half*)(gb + OFF_CH), *cl = (__half*)(gb + OFF_CL);

    cudaFuncSetAttribute(gemm_mma<0>, cudaFuncAttributeMaxDynamicSharedMemorySize, GEMM_SMEM);
    cudaFuncSetAttribute(gemm_mma<1>, cudaFuncAttributeMaxDynamicSharedMemorySize, GEMM_SMEM);
    cudaFuncSetAttribute(attn_mma, cudaFuncAttributeMaxDynamicSharedMemorySize, ATTN_SMEM);

    // all conversions in one launch: 3 inputs + 4 weights -> fp16 single
    ConvArgs ca;
    ca.s[0] = (const float4*)Q;    ca.o[0] = (uint4*)xf[0]; ca.nch[0] = NX/8;
    ca.s[1] = (const float4*)K;    ca.o[1] = (uint4*)xf[1]; ca.nch[1] = NX/8;
    ca.s[2] = (const float4*)V;    ca.o[2] = (uint4*)xf[2]; ca.nch[2] = NX/8;
    ca.s[3] = (const float4*)Wq_w; ca.o[3] = (uint4*)wf[0]; ca.nch[3] = NW/8;
    ca.s[4] = (const float4*)Wk_w; ca.o[4] = (uint4*)wf[1]; ca.nch[4] = NW/8;
    ca.s[5] = (const float4*)Wv_w; ca.o[5] = (uint4*)wf[2]; ca.nch[5] = NW/8;
    ca.s[6] = (const float4*)Wo_w; ca.o[6] = (uint4*)wf[3]; ca.nch[6] = NW/8;
    conv_multi<<<dim3(NX/8/256, 7), 256>>>(ca);

    // batched QKV projections: A = fp16 single (ASPLIT=0)
    GemmArgs gqkv;
    gqkv.ah[0] = xf[0]; gqkv.al[0] = nullptr; gqkv.wf[0] = wf[0];
    gqkv.bias[0] = Wq_b; gqkv.yf[0] = nullptr; gqkv.yh[0] = qh; gqkv.yl[0] = ql; gqkv.mode[0] = 3;
    gqkv.ah[1] = xf[1]; gqkv.al[1] = nullptr; gqkv.wf[1] = wf[1];
    gqkv.bias[1] = Wk_b; gqkv.yf[1] = nullptr; gqkv.yh[1] = kf; gqkv.yl[1] = nullptr; gqkv.mode[1] = 4;
    gqkv.ah[2] = xf[2]; gqkv.al[2] = nullptr; gqkv.wf[2] = wf[2];
    gqkv.bias[2] = Wv_b; gqkv.yf[2] = nullptr; gqkv.yh[2] = vf; gqkv.yl[2] = nullptr; gqkv.mode[2] = 1;
    gemm_mma<0><<<dim3(DM/128, MTOT/256, 3), 256, GEMM_SMEM>>>(gqkv);

    dim3 agrid(SEQ/128, NBH);
    attn_mma<<<agrid, 256, ATTN_SMEM>>>(qh, ql, kf, vf, ch, cl);

    // Wo: A = ctx fp16 split-2 (ASPLIT=1)
    GemmArgs go;
    go.ah[0] = ch; go.al[0] = cl; go.wf[0] = wf[3];
    go.bias[0] = Wo_b; go.yf[0] = out; go.yh[0] = nullptr; go.yl[0] = nullptr; go.mode[0] = 0;
    go.ah[1] = go.ah[0]; go.al[1] = go.al[0]; go.wf[1] = go.wf[0];
    go.bias[1] = go.bias[0]; go.yf[1] = go.yf[0]; go.yh[1] = nullptr; go.yl[1] = nullptr; go.mode[1] = 0;
    go.ah[2] = go.ah[0]; go.al[2] = go.al[0]; go.wf[2] = go.wf[0];
    go.bias[2] = go.bias[0]; go.yf[2] = go.yf[0]; go.yh[2] = nullptr; go.yl[2] = nullptr; go.mode[2] = 0;
    gemm_mma<1><<<dim3(DM/128, MTOT/256, 1), 256, GEMM_SMEM>>>(go);
}

// round 14
// speedup vs baseline: 2.4908x; 1.2325x over previous
#include <cuda_runtime.h>
#include <cuda_bf16.h>
#include <cuda_fp16.h>
#include <stdint.h>

#define DM 1024
#define NH 16
#define DK 64
#define SEQ 2048
#define MTOT 4096
#define NBH 32
#define NX (MTOT*DM)
#define NW (DM*DM)

// scratch arena (raw 2-byte storage)
__device__ __nv_bfloat16 g_buf[14ull*NX + 8ull*NW];

#define OFF_XQ  0ull                 /* fp16 single inputs */
#define OFF_XK  (1ull*NX)
#define OFF_XV  (2ull*NX)
#define OFF_W   (6ull*NX)
#define OFF_QF  (OFF_W + 8ull*NW)    /* fp16 single */
#define OFF_KF  (OFF_QF + 2ull*NX)
#define OFF_VF  (OFF_QF + 4ull*NX)   /* fp16 single, transposed [b,h,d,s] */
#define OFF_CF  (OFF_QF + 6ull*NX)   /* ctx fp16 single */

static __device__ __forceinline__ uint32_t smem_u32(const void* p) {
    uint32_t a;
    asm("{ .reg .u64 t; cvta.to.shared.u64 t, %1; cvt.u32.u64 %0, t; }" : "=r"(a) : "l"(p));
    return a;
}

#define MMAH(C, A, B) asm volatile( \
    "mma.sync.aligned.m16n8k16.row.col.f32.f16.f16.f32 " \
    "{%0,%1,%2,%3}, {%4,%5,%6,%7}, {%8,%9}, {%0,%1,%2,%3};" \
    : "+f"((C)[0]), "+f"((C)[1]), "+f"((C)[2]), "+f"((C)[3]) \
    : "r"((A)[0]), "r"((A)[1]), "r"((A)[2]), "r"((A)[3]), \
      "r"((B)[0]), "r"((B)[1]))

#define LDM4(R, ADDR) asm volatile( \
    "ldmatrix.sync.aligned.m8n8.x4.shared.b16 {%0,%1,%2,%3}, [%4];" \
    : "=r"((R)[0]), "=r"((R)[1]), "=r"((R)[2]), "=r"((R)[3]) : "r"(ADDR))

#define CP16(d, s) asm volatile("cp.async.cg.shared.global [%0], [%1], 16;" :: "r"(d), "l"(s))
#define CPC()   asm volatile("cp.async.commit_group;")
#define CPW(n)  asm volatile("cp.async.wait_group %0;" :: "n"(n))

#define SWC(row, ch) (((row) << 6) + ((((ch) ^ (((row) >> 1) & 3))) << 4))
#define SWK(row, ch) (((row) << 7) + ((((ch) ^ ((row) & 7))) << 4))

static __device__ __forceinline__ void split2h(float x0, float x1,
                                               uint32_t& hp, uint32_t& lp) {
    __half h0 = __float2half(x0), h1 = __float2half(x1);
    __half l0 = __float2half(x0 - __half2float(h0));
    __half l1 = __float2half(x1 - __half2float(h1));
    hp = (uint32_t)__half_as_ushort(h0) | ((uint32_t)__half_as_ushort(h1) << 16);
    lp = (uint32_t)__half_as_ushort(l0) | ((uint32_t)__half_as_ushort(l1) << 16);
}
static __device__ __forceinline__ uint32_t pack_h2(float x0, float x1) {
    __half2 h = __floats2half2_rn(x0, x1);
    return *(uint32_t*)&h;
}

// ---------------------------------------------------------------------------
// unified fp32 -> fp16 single conversion for up to 7 tensors (grid.y selects)
struct ConvArgs {
    const float4* s[7];
    uint4* o[7];
    int nch[7];
};
__global__ void conv_multi(ConvArgs a)
{
    const int y = blockIdx.y;
    int i = blockIdx.x * blockDim.x + threadIdx.x;
    if (i >= a.nch[y]) return;
    const float4* src = a.s[y];
    float4 p = src[i*2], q = src[i*2+1];
    uint4 O;
    O.x = pack_h2(p.x, p.y);
    O.y = pack_h2(p.z, p.w);
    O.z = pack_h2(q.x, q.y);
    O.w = pack_h2(q.z, q.w);
    a.o[y][i] = O;
}

// ---------------------------------------------------------------------------
// Batched GEMM: Y = A @ W^T + bias. A, W = fp16 single (1 MMA per product).
// CTA 256x128, k-step 64 (two 32-k sub-blocks), 2-stage, 1 sync/iter.
// mode 0: fp32 out. mode 1: V fp16 single transposed [b,h,d,s].
// mode 3: rownorm + fp16 single [b,h,s,d] (Q and K).
// ---------------------------------------------------------------------------
struct GemmArgs {
    const __half* ah[3];
    const __half* wf[3];
    const float* bias[3];
    float* yf[3];
    __half* yh[3];
    int mode[3];
};
#define G_SUB    24576    /* A 16K + B 8K */
#define G_STAGE  49152
#define GEMM_SMEM (2*G_STAGE)   /* 98304 */
__global__ void __launch_bounds__(256, 1) gemm_mma(GemmArgs ga)
{
    extern __shared__ char sm[];
    const uint32_t sb = smem_u32(sm);
    const int z = blockIdx.z;
    const int t = threadIdx.x, lane = t & 31, w = t >> 5;
    const int wm = w & 3, wn = w >> 2;
    const int n0 = blockIdx.x * 128, m0 = blockIdx.y * 256;
    const int mode = ga.mode[z];
    const float* bias = ga.bias[z];

    const __half* aSrc = ga.ah[z] + (size_t)m0 * DM;
    const __half* bSrc = ga.wf[z] + (size_t)n0 * DM;

    const int lrow = t >> 2, lch = t & 3;

#define G_LOAD(kt, st) do { \
    _Pragma("unroll") \
    for (int s_2 = 0; s_2 < 2; s_2++) { \
        uint32_t ab = sb + (st)*G_STAGE + s_2*G_SUB; \
        _Pragma("unroll") \
        for (int j_ = 0; j_ < 4; j_++) { \
            int r_ = lrow + j_*64; \
            CP16(ab + SWC(r_, lch), aSrc + (size_t)r_ * DM + (kt) + s_2*32 + lch*8); \
        } \
        uint32_t bb = ab + 16384; \
        _Pragma("unroll") \
        for (int j_ = 0; j_ < 2; j_++) { \
            int r_ = lrow + j_*64; \
            CP16(bb + SWC(r_, lch), bSrc + (size_t)r_ * DM + (kt) + s_2*32 + lch*8); \
        } \
    } \
} while (0)

    float acc[4][8][4];
    #pragma unroll
    for (int i = 0; i < 4; i++)
        #pragma unroll
        for (int j = 0; j < 8; j++)
            #pragma unroll
            for (int k = 0; k < 4; k++) acc[i][j][k] = 0.f;

    const int aRow0 = wm*64 + (lane & 15);
    const int aChH  = lane >> 4;
    const int bRowOff = wn*64 + (lane & 7) + ((lane >> 4) << 3);
    const int bChH  = (lane >> 3) & 1;

    G_LOAD(0, 0);  CPC();

    #pragma unroll 1
    for (int kc = 0; kc < 16; kc++) {
        const int st = kc & 1;
        CPW(0);
        __syncthreads();
        if (kc + 1 < 16) G_LOAD((kc + 1) * 64, st ^ 1);
        CPC();

        #pragma unroll
        for (int sub = 0; sub < 2; sub++) {
            const uint32_t uA = sb + st*G_STAGE + sub*G_SUB;
            const uint32_t uB = uA + 16384;
            #pragma unroll
            for (int ks = 0; ks < 2; ks++) {
                const int c = ks*2 + aChH;
                uint32_t aF[4][4];
                #pragma unroll
                for (int mt = 0; mt < 4; mt++)
                    LDM4(aF[mt], uA + SWC(aRow0 + mt*16, c));
                const int cb = ks*2 + bChH;
                #pragma unroll
                for (int nt2 = 0; nt2 < 4; nt2++) {
                    int r = bRowOff + nt2*16;
                    uint32_t rv[4];
                    LDM4(rv, uB + SWC(r, cb));
                    uint32_t b0[2] = {rv[0], rv[1]}, b1[2] = {rv[2], rv[3]};
                    const int nA = nt2*2, nB = nt2*2 + 1;
                    #pragma unroll
                    for (int mt = 0; mt < 4; mt++) {
                        MMAH(acc[mt][nA], aF[mt], b0);
                        MMAH(acc[mt][nB], aF[mt], b1);
                    }
                }
            }
        }
    }

    // ---- epilogue ----
    float* Yf = ga.yf[z];
    __half* Yh = ga.yh[z];
    const int g = lane >> 2, tig = lane & 3;
    #pragma unroll
    for (int mt = 0; mt < 4; mt++) {
        const int r0 = m0 + wm*64 + mt*16 + g;
        float v[2][8][2];
        #pragma unroll
        for (int nt = 0; nt < 8; nt++) {
            int col = n0 + wn*64 + nt*8 + tig*2;
            float b0v = bias[col], b1v = bias[col + 1];
            v[0][nt][0] = acc[mt][nt][0] + b0v;
            v[0][nt][1] = acc[mt][nt][1] + b1v;
            v[1][nt][0] = acc[mt][nt][2] + b0v;
            v[1][nt][1] = acc[mt][nt][3] + b1v;
        }
        if (mode == 0) {
            #pragma unroll
            for (int rr = 0; rr < 2; rr++) {
                int r = r0 + rr*8;
                #pragma unroll
                for (int nt = 0; nt < 8; nt++) {
                    int col = n0 + wn*64 + nt*8 + tig*2;
                    *(float2*)(Yf + (size_t)r * DM + col) =
                        make_float2(v[rr][nt][0], v[rr][nt][1]);
                }
            }
        } else {
            if (mode == 3) {
                #pragma unroll
                for (int rr = 0; rr < 2; rr++) {
                    float ss = 0.f;
                    #pragma unroll
                    for (int nt = 0; nt < 8; nt++)
                        ss += v[rr][nt][0]*v[rr][nt][0] + v[rr][nt][1]*v[rr][nt][1];
                    ss += __shfl_xor_sync(0xffffffffu, ss, 1);
                    ss += __shfl_xor_sync(0xffffffffu, ss, 2);
                    float inv = rsqrtf(ss + 1e-8f);
                    #pragma unroll
                    for (int nt = 0; nt < 8; nt++) {
                        v[rr][nt][0] *= inv;
                        v[rr][nt][1] *= inv;
                    }
                }
            }
            const int h_ = (n0 >> 6) + wn;
            const int b_ = r0 >> 11;
            #pragma unroll
            for (int rr = 0; rr < 2; rr++) {
                const int s_ = (r0 + rr*8) & 2047;
                if (mode == 1) {
                    const size_t base = (size_t)(b_ * NH + h_) * DK;
                    #pragma unroll
                    for (int nt = 0; nt < 8; nt++) {
                        int d = nt*8 + tig*2;
                        Yh[(base + d    ) * SEQ + s_] = __float2half(v[rr][nt][0]);
                        Yh[(base + d + 1) * SEQ + s_] = __float2half(v[rr][nt][1]);
                    }
                } else {
                    const size_t base = ((size_t)(b_ * NH + h_) * SEQ + s_) * DK;
                    #pragma unroll
                    for (int nt = 0; nt < 8; nt++)
                        *(uint32_t*)(Yh + base + nt*8 + tig*2) =
                            pack_h2(v[rr][nt][0], v[rr][nt][1]);
                }
            }
        }
    }
#undef G_LOAD
}

// ---------------------------------------------------------------------------
// Attention: CTA = (bh, 128-q tile), 8 warps x 16 q-rows, 64-key chunks,
// 2-stage cp.async, 1 sync/iter. All operands fp16 single.
// ---------------------------------------------------------------------------
#define A_QARR  16384
#define A_KARR  8192
#define A_STAGE (2*A_KARR)
#define ATTN_SMEM (A_QARR + 2*A_STAGE)   /* 49152 */
__global__ void __launch_bounds__(256, 2) attn_mma(
    const __half* __restrict__ qfp, const __half* __restrict__ kfp,
    const __half* __restrict__ vfp, __half* __restrict__ cf)
{
    extern __shared__ char sm[];
    const uint32_t sb = smem_u32(sm);
    const int t = threadIdx.x, lane = t & 31, w = t >> 5;
    const int q0 = blockIdx.x * 128;
    const int bh = blockIdx.y;
    const size_t base = (size_t)bh * SEQ * DK;

    const __half* Ksrc = kfp + base;
    const __half* Vsrc = vfp + base;

    const int krow = t >> 2, kch = t & 3;

#define A_LOADKV(kt, st) do { \
    uint32_t kb = sb + A_QARR + (st)*A_STAGE; \
    CP16(kb + SWK(krow, kch),     Ksrc + (size_t)((kt) + krow) * DK + kch*8); \
    CP16(kb + SWK(krow, kch + 4), Ksrc + (size_t)((kt) + krow) * DK + (kch + 4)*8); \
    uint32_t vb = kb + A_KARR; \
    CP16(vb + SWK(krow, kch),     Vsrc + (size_t)krow * SEQ + (kt) + kch*8); \
    CP16(vb + SWK(krow, kch + 4), Vsrc + (size_t)krow * SEQ + (kt) + (kch + 4)*8); \
} while (0)

    // Q loads: 128 rows x 8 chunks, fp16 single
    {
        const __half* Qsrc = qfp + base;
        #pragma unroll
        for (int i = 0; i < 4; i++) {
            int c = t + i*256, row = c >> 3, chn = c & 7;
            CP16(sb + SWK(row, chn), Qsrc + (size_t)(q0 + row) * DK + chn*8);
        }
    }
    A_LOADKV(0, 0);  CPC();

    const int aRow = w*16 + (lane & 15);
    const int aChH = lane >> 4;
    const int bRowOff = (lane & 7) + ((lane >> 4) << 3);
    const int bChH = (lane >> 3) & 1;

    float o[8][4];
    #pragma unroll
    for (int i = 0; i < 8; i++)
        #pragma unroll
        for (int j = 0; j < 4; j++) o[i][j] = 0.f;

    #pragma unroll 1
    for (int kc = 0; kc < 32; kc++) {
        const int st = kc & 1;
        CPW(0);
        __syncthreads();
        if (kc + 1 < 32) A_LOADKV((kc + 1) * 64, st ^ 1);
        CPC();

        const uint32_t uKf = sb + A_QARR + st*A_STAGE;
        const uint32_t uVf = uKf + A_KARR;

        float s[8][4];
        #pragma unroll
        for (int i = 0; i < 8; i++)
            #pragma unroll
            for (int j = 0; j < 4; j++) s[i][j] = 0.f;

        #pragma unroll
        for (int ks = 0; ks < 4; ks++) {
            uint32_t aQ[4];
            LDM4(aQ, sb + SWK(aRow, ks*2 + aChH));
            const int cb = ks*2 + bChH;
            #pragma unroll
            for (int nt2 = 0; nt2 < 4; nt2++) {
                int r = bRowOff + nt2*16;
                uint32_t rk[4];
                LDM4(rk, uKf + SWK(r, cb));
                uint32_t b0[2] = {rk[0], rk[1]}, b1[2] = {rk[2], rk[3]};
                MMAH(s[nt2*2],     aQ, b0);
                MMAH(s[nt2*2 + 1], aQ, b1);
            }
        }

        #pragma unroll
        for (int kt2 = 0; kt2 < 4; kt2++) {
            uint32_t aP[4];
            aP[0] = pack_h2(s[2*kt2][0]*s[2*kt2][0],     s[2*kt2][1]*s[2*kt2][1]);
            aP[1] = pack_h2(s[2*kt2][2]*s[2*kt2][2],     s[2*kt2][3]*s[2*kt2][3]);
            aP[2] = pack_h2(s[2*kt2+1][0]*s[2*kt2+1][0], s[2*kt2+1][1]*s[2*kt2+1][1]);
            aP[3] = pack_h2(s[2*kt2+1][2]*s[2*kt2+1][2], s[2*kt2+1][3]*s[2*kt2+1][3]);
            const int cb = kt2*2 + bChH;
            #pragma unroll
            for (int nt2 = 0; nt2 < 4; nt2++) {
                int r = bRowOff + nt2*16;
                uint32_t rv[4];
                LDM4(rv, uVf + SWK(r, cb));
                uint32_t b0[2] = {rv[0], rv[1]}, b1[2] = {rv[2], rv[3]};
                MMAH(o[nt2*2], aP, b0);
                MMAH(o[nt2*2 + 1], aP, b1);
            }
        }
    }

    // ctx epilogue: fp16 single, [b, s, DM]
    const int g = lane >> 2, tig = lane & 3;
    const int r0 = q0 + w*16 + g;
    const int b_ = bh >> 4, h_ = bh & 15;
    #pragma unroll
    for (int rr = 0; rr < 2; rr++) {
        const int s_ = r0 + rr*8;
        const size_t ob = ((size_t)b_ * SEQ + s_) * DM + h_ * DK;
        #pragma unroll
        for (int nt = 0; nt < 8; nt++)
            *(uint32_t*)(cf + ob + nt*8 + tig*2) =
                pack_h2(o[nt][rr*2], o[nt][rr*2+1]);
    }
#undef A_LOADKV
}

// ---------------------------------------------------------------------------
extern "C" void kernel_launch(void* const* d_in, const int* in_sizes, int n_in,
                              void* d_out, int out_size)
{
    const float* Q    = (const float*)d_in[0];
    const float* K    = (const float*)d_in[1];
    const float* V    = (const float*)d_in[2];
    const float* Wq_w = (const float*)d_in[3];
    const float* Wq_b = (const float*)d_in[4];
    const float* Wk_w = (const float*)d_in[5];
    const float* Wk_b = (const float*)d_in[6];
    const float* Wv_w = (const float*)d_in[7];
    const float* Wv_b = (const float*)d_in[8];
    const float* Wo_w = (const float*)d_in[9];
    const float* Wo_b = (const float*)d_in[10];
    float* out = (float*)d_out;

    __nv_bfloat16* gb;
    cudaGetSymbolAddress((void**)&gb, g_buf);

    __half* xf[3] = { (__half*)(gb + OFF_XQ), (__half*)(gb + OFF_XK), (__half*)(gb + OFF_XV) };
    __half* wf[4];
    for (int i = 0; i < 4; i++) wf[i] = (__half*)(gb + OFF_W) + (size_t)i * NW;
    __half *qf = (__half*)(gb + OFF_QF);
    __half *kf = (__half*)(gb + OFF_KF);
    __half *vf = (__half*)(gb + OFF_VF);
    __half *cf = (__half*)(gb + OFF_CF);

    cudaFuncSetAttribute(gemm_mma, cudaFuncAttributeMaxDynamicSharedMemorySize, GEMM_SMEM);
    cudaFuncSetAttribute(attn_mma, cudaFuncAttributeMaxDynamicSharedMemorySize, ATTN_SMEM);

    ConvArgs ca;
    ca.s[0] = (const float4*)Q;    ca.o[0] = (uint4*)xf[0]; ca.nch[0] = NX/8;
    ca.s[1] = (const float4*)K;    ca.o[1] = (uint4*)xf[1]; ca.nch[1] = NX/8;
    ca.s[2] = (const float4*)V;    ca.o[2] = (uint4*)xf[2]; ca.nch[2] = NX/8;
    ca.s[3] = (const float4*)Wq_w; ca.o[3] = (uint4*)wf[0]; ca.nch[3] = NW/8;
    ca.s[4] = (const float4*)Wk_w; ca.o[4] = (uint4*)wf[1]; ca.nch[4] = NW/8;
    ca.s[5] = (const float4*)Wv_w; ca.o[5] = (uint4*)wf[2]; ca.nch[5] = NW/8;
    ca.s[6] = (const float4*)Wo_w; ca.o[6] = (uint4*)wf[3]; ca.nch[6] = NW/8;
    conv_multi<<<dim3(NX/8/256, 7), 256>>>(ca);

    // batched QKV projections (all fp16 single)
    GemmArgs gqkv;
    gqkv.ah[0] = xf[0]; gqkv.wf[0] = wf[0];
    gqkv.bias[0] = Wq_b; gqkv.yf[0] = nullptr; gqkv.yh[0] = qf; gqkv.mode[0] = 3;
    gqkv.ah[1] = xf[1]; gqkv.wf[1] = wf[1];
    gqkv.bias[1] = Wk_b; gqkv.yf[1] = nullptr; gqkv.yh[1] = kf; gqkv.mode[1] = 3;
    gqkv.ah[2] = xf[2]; gqkv.wf[2] = wf[2];
    gqkv.bias[2] = Wv_b; gqkv.yf[2] = nullptr; gqkv.yh[2] = vf; gqkv.mode[2] = 1;
    gemm_mma<<<dim3(DM/128, MTOT/256, 3), 256, GEMM_SMEM>>>(gqkv);

    dim3 agrid(SEQ/128, NBH);
    attn_mma<<<agrid, 256, ATTN_SMEM>>>(qf, kf, vf, cf);

    // Wo GEMM (fp16 single)
    GemmArgs go;
    go.ah[0] = cf; go.wf[0] = wf[3];
    go.bias[0] = Wo_b; go.yf[0] = out; go.yh[0] = nullptr; go.mode[0] = 0;
    go.ah[1] = go.ah[0]; go.wf[1] = go.wf[0];
    go.bias[1] = go.bias[0]; go.yf[1] = go.yf[0]; go.yh[1] = nullptr; go.mode[1] = 0;
    go.ah[2] = go.ah[0]; go.wf[2] = go.wf[0];
    go.bias[2] = go.bias[0]; go.yf[2] = go.yf[0]; go.yh[2] = nullptr; go.mode[2] = 0;
    gemm_mma<<<dim3(DM/128, MTOT/256, 1), 256, GEMM_SMEM>>>(go);
}

// round 15
// speedup vs baseline: 2.5804x; 1.0360x over previous
#include <cuda_runtime.h>
#include <cuda_bf16.h>
#include <cuda_fp16.h>
#include <stdint.h>

#define DM 1024
#define NH 16
#define DK 64
#define SEQ 2048
#define MTOT 4096
#define NBH 32
#define NX (MTOT*DM)
#define NW (DM*DM)

// scratch arena (raw 2-byte storage)
__device__ __nv_bfloat16 g_buf[14ull*NX + 8ull*NW];

#define OFF_XQ  0ull
#define OFF_XK  (1ull*NX)
#define OFF_XV  (2ull*NX)
#define OFF_W   (6ull*NX)
#define OFF_QF  (OFF_W + 8ull*NW)
#define OFF_KF  (OFF_QF + 2ull*NX)
#define OFF_VF  (OFF_QF + 4ull*NX)   /* fp16, transposed [b,h,d,s] */
#define OFF_CF  (OFF_QF + 6ull*NX)

static __device__ __forceinline__ uint32_t smem_u32(const void* p) {
    uint32_t a;
    asm("{ .reg .u64 t; cvta.to.shared.u64 t, %1; cvt.u32.u64 %0, t; }" : "=r"(a) : "l"(p));
    return a;
}

#define MMAH(C, A, B) asm volatile( \
    "mma.sync.aligned.m16n8k16.row.col.f32.f16.f16.f32 " \
    "{%0,%1,%2,%3}, {%4,%5,%6,%7}, {%8,%9}, {%0,%1,%2,%3};" \
    : "+f"((C)[0]), "+f"((C)[1]), "+f"((C)[2]), "+f"((C)[3]) \
    : "r"((A)[0]), "r"((A)[1]), "r"((A)[2]), "r"((A)[3]), \
      "r"((B)[0]), "r"((B)[1]))

#define LDM4(R, ADDR) asm volatile( \
    "ldmatrix.sync.aligned.m8n8.x4.shared.b16 {%0,%1,%2,%3}, [%4];" \
    : "=r"((R)[0]), "=r"((R)[1]), "=r"((R)[2]), "=r"((R)[3]) : "r"(ADDR))

#define CP16(d, s) asm volatile("cp.async.cg.shared.global [%0], [%1], 16;" :: "r"(d), "l"(s))
#define CPC()   asm volatile("cp.async.commit_group;")
#define CPW(n)  asm volatile("cp.async.wait_group %0;" :: "n"(n))

#define SWC(row, ch) (((row) << 6) + ((((ch) ^ (((row) >> 1) & 3))) << 4))
#define SWK(row, ch) (((row) << 7) + ((((ch) ^ ((row) & 7))) << 4))

static __device__ __forceinline__ uint32_t pack_h2(float x0, float x1) {
    __half2 h = __floats2half2_rn(x0, x1);
    return *(uint32_t*)&h;
}

// ---------------------------------------------------------------------------
struct ConvArgs {
    const float4* s[7];
    uint4* o[7];
    int nch[7];
};
__global__ void conv_multi(ConvArgs a)
{
    const int y = blockIdx.y;
    int i = blockIdx.x * blockDim.x + threadIdx.x;
    if (i >= a.nch[y]) return;
    const float4* src = a.s[y];
    float4 p = src[i*2], q = src[i*2+1];
    uint4 O;
    O.x = pack_h2(p.x, p.y);
    O.y = pack_h2(p.z, p.w);
    O.z = pack_h2(q.x, q.y);
    O.w = pack_h2(q.z, q.w);
    a.o[y][i] = O;
}

// ---------------------------------------------------------------------------
// Batched GEMM: Y = A @ W^T + bias. fp16 single operands.
// CTA 128x128, warp tile 32x64, k-step 64 (two 32-k subs), 2-stage, 2 CTA/SM.
// mode 0: fp32 out. mode 1: V fp16 transposed. mode 3: rownorm + fp16 [b,h,s,d].
// ---------------------------------------------------------------------------
struct GemmArgs {
    const __half* ah[3];
    const __half* wf[3];
    const float* bias[3];
    float* yf[3];
    __half* yh[3];
    int mode[3];
};
#define G_SUB    16384    /* A 8K + B 8K */
#define G_STAGE  32768
#define GEMM_SMEM (2*G_STAGE)   /* 65536 */
__global__ void __launch_bounds__(256, 2) gemm_mma(GemmArgs ga)
{
    extern __shared__ char sm[];
    const uint32_t sb = smem_u32(sm);
    const int z = blockIdx.z;
    const int t = threadIdx.x, lane = t & 31, w = t >> 5;
    const int wm = w & 3, wn = w >> 2;
    const int n0 = blockIdx.x * 128, m0 = blockIdx.y * 128;
    const int mode = ga.mode[z];
    const float* bias = ga.bias[z];

    const __half* aSrc = ga.ah[z] + (size_t)m0 * DM;
    const __half* bSrc = ga.wf[z] + (size_t)n0 * DM;

    const int lrow = t >> 2, lch = t & 3;

#define G_LOAD(kt, st) do { \
    _Pragma("unroll") \
    for (int s_2 = 0; s_2 < 2; s_2++) { \
        uint32_t ab = sb + (st)*G_STAGE + s_2*G_SUB; \
        _Pragma("unroll") \
        for (int j_ = 0; j_ < 2; j_++) { \
            int r_ = lrow + j_*64; \
            CP16(ab + SWC(r_, lch), aSrc + (size_t)r_ * DM + (kt) + s_2*32 + lch*8); \
        } \
        uint32_t bb = ab + 8192; \
        _Pragma("unroll") \
        for (int j_ = 0; j_ < 2; j_++) { \
            int r_ = lrow + j_*64; \
            CP16(bb + SWC(r_, lch), bSrc + (size_t)r_ * DM + (kt) + s_2*32 + lch*8); \
        } \
    } \
} while (0)

    float acc[2][8][4];
    #pragma unroll
    for (int i = 0; i < 2; i++)
        #pragma unroll
        for (int j = 0; j < 8; j++)
            #pragma unroll
            for (int k = 0; k < 4; k++) acc[i][j][k] = 0.f;

    const int aRow0 = wm*32 + (lane & 15);
    const int aChH  = lane >> 4;
    const int bRowOff = wn*64 + (lane & 7) + ((lane >> 4) << 3);
    const int bChH  = (lane >> 3) & 1;

    G_LOAD(0, 0);  CPC();

    #pragma unroll 1
    for (int kc = 0; kc < 16; kc++) {
        const int st = kc & 1;
        CPW(0);
        __syncthreads();
        if (kc + 1 < 16) G_LOAD((kc + 1) * 64, st ^ 1);
        CPC();

        #pragma unroll
        for (int sub = 0; sub < 2; sub++) {
            const uint32_t uA = sb + st*G_STAGE + sub*G_SUB;
            const uint32_t uB = uA + 8192;
            #pragma unroll
            for (int ks = 0; ks < 2; ks++) {
                const int c = ks*2 + aChH;
                uint32_t aF[2][4];
                LDM4(aF[0], uA + SWC(aRow0,      c));
                LDM4(aF[1], uA + SWC(aRow0 + 16, c));
                const int cb = ks*2 + bChH;
                #pragma unroll
                for (int nt2 = 0; nt2 < 4; nt2++) {
                    int r = bRowOff + nt2*16;
                    uint32_t rv[4];
                    LDM4(rv, uB + SWC(r, cb));
                    uint32_t b0[2] = {rv[0], rv[1]}, b1[2] = {rv[2], rv[3]};
                    const int nA = nt2*2, nB = nt2*2 + 1;
                    MMAH(acc[0][nA], aF[0], b0);
                    MMAH(acc[0][nB], aF[0], b1);
                    MMAH(acc[1][nA], aF[1], b0);
                    MMAH(acc[1][nB], aF[1], b1);
                }
            }
        }
    }

    // ---- epilogue ----
    float* Yf = ga.yf[z];
    __half* Yh = ga.yh[z];
    const int g = lane >> 2, tig = lane & 3;
    #pragma unroll
    for (int mt = 0; mt < 2; mt++) {
        const int r0 = m0 + wm*32 + mt*16 + g;
        float v[2][8][2];
        #pragma unroll
        for (int nt = 0; nt < 8; nt++) {
            int col = n0 + wn*64 + nt*8 + tig*2;
            float b0v = bias[col], b1v = bias[col + 1];
            v[0][nt][0] = acc[mt][nt][0] + b0v;
            v[0][nt][1] = acc[mt][nt][1] + b1v;
            v[1][nt][0] = acc[mt][nt][2] + b0v;
            v[1][nt][1] = acc[mt][nt][3] + b1v;
        }
        if (mode == 0) {
            #pragma unroll
            for (int rr = 0; rr < 2; rr++) {
                int r = r0 + rr*8;
                #pragma unroll
                for (int nt = 0; nt < 8; nt++) {
                    int col = n0 + wn*64 + nt*8 + tig*2;
                    *(float2*)(Yf + (size_t)r * DM + col) =
                        make_float2(v[rr][nt][0], v[rr][nt][1]);
                }
            }
        } else {
            if (mode == 3) {
                #pragma unroll
                for (int rr = 0; rr < 2; rr++) {
                    float ss = 0.f;
                    #pragma unroll
                    for (int nt = 0; nt < 8; nt++)
                        ss += v[rr][nt][0]*v[rr][nt][0] + v[rr][nt][1]*v[rr][nt][1];
                    ss += __shfl_xor_sync(0xffffffffu, ss, 1);
                    ss += __shfl_xor_sync(0xffffffffu, ss, 2);
                    float inv = rsqrtf(ss + 1e-8f);
                    #pragma unroll
                    for (int nt = 0; nt < 8; nt++) {
                        v[rr][nt][0] *= inv;
                        v[rr][nt][1] *= inv;
                    }
                }
            }
            const int h_ = (n0 >> 6) + wn;
            const int b_ = r0 >> 11;
            #pragma unroll
            for (int rr = 0; rr < 2; rr++) {
                const int s_ = (r0 + rr*8) & 2047;
                if (mode == 1) {
                    const size_t base = (size_t)(b_ * NH + h_) * DK;
                    #pragma unroll
                    for (int nt = 0; nt < 8; nt++) {
                        int d = nt*8 + tig*2;
                        Yh[(base + d    ) * SEQ + s_] = __float2half(v[rr][nt][0]);
                        Yh[(base + d + 1) * SEQ + s_] = __float2half(v[rr][nt][1]);
                    }
                } else {
                    const size_t base = ((size_t)(b_ * NH + h_) * SEQ + s_) * DK;
                    #pragma unroll
                    for (int nt = 0; nt < 8; nt++)
                        *(uint32_t*)(Yh + base + nt*8 + tig*2) =
                            pack_h2(v[rr][nt][0], v[rr][nt][1]);
                }
            }
        }
    }
#undef G_LOAD
}

// ---------------------------------------------------------------------------
// Attention: 128-thread CTA, 4 warps x 32 q-rows (mt=2), q-tile 128,
// 64-key chunks, 2-stage cp.async, 1 sync/iter. All operands fp16 single.
// ---------------------------------------------------------------------------
#define A_QARR  16384
#define A_KARR  8192
#define A_STAGE (2*A_KARR)
#define ATTN_SMEM (A_QARR + 2*A_STAGE)   /* 49152 */
__global__ void __launch_bounds__(128, 2) attn_mma(
    const __half* __restrict__ qfp, const __half* __restrict__ kfp,
    const __half* __restrict__ vfp, __half* __restrict__ cf)
{
    extern __shared__ char sm[];
    const uint32_t sb = smem_u32(sm);
    const int t = threadIdx.x, lane = t & 31, w = t >> 5;
    const int q0 = blockIdx.x * 128;
    const int bh = blockIdx.y;
    const size_t base = (size_t)bh * SEQ * DK;

    const __half* Ksrc = kfp + base;
    const __half* Vsrc = vfp + base;

    const int krow = t >> 1, kc0 = (t & 1) * 4;   // 64 rows, 4 chunks each

#define A_LOADKV(kt, st) do { \
    uint32_t kb = sb + A_QARR + (st)*A_STAGE; \
    _Pragma("unroll") \
    for (int c_ = 0; c_ < 4; c_++) \
        CP16(kb + SWK(krow, kc0 + c_), Ksrc + (size_t)((kt) + krow) * DK + (kc0 + c_)*8); \
    uint32_t vb = kb + A_KARR; \
    _Pragma("unroll") \
    for (int c_ = 0; c_ < 4; c_++) \
        CP16(vb + SWK(krow, kc0 + c_), Vsrc + (size_t)krow * SEQ + (kt) + (kc0 + c_)*8); \
} while (0)

    // Q loads: 128 rows x 8 chunks
    {
        const __half* Qsrc = qfp + base;
        #pragma unroll
        for (int i = 0; i < 8; i++) {
            int c = t + i*128, row = c >> 3, chn = c & 7;
            CP16(sb + SWK(row, chn), Qsrc + (size_t)(q0 + row) * DK + chn*8);
        }
    }
    A_LOADKV(0, 0);  CPC();

    const int aRow0 = w*32 + (lane & 15);
    const int aChH = lane >> 4;
    const int bRowOff = (lane & 7) + ((lane >> 4) << 3);
    const int bChH = (lane >> 3) & 1;

    float o[2][8][4];
    #pragma unroll
    for (int m = 0; m < 2; m++)
        #pragma unroll
        for (int i = 0; i < 8; i++)
            #pragma unroll
            for (int j = 0; j < 4; j++) o[m][i][j] = 0.f;

    #pragma unroll 1
    for (int kc = 0; kc < 32; kc++) {
        const int st = kc & 1;
        CPW(0);
        __syncthreads();
        if (kc + 1 < 32) A_LOADKV((kc + 1) * 64, st ^ 1);
        CPC();

        const uint32_t uKf = sb + A_QARR + st*A_STAGE;
        const uint32_t uVf = uKf + A_KARR;

        float s[2][8][4];
        #pragma unroll
        for (int m = 0; m < 2; m++)
            #pragma unroll
            for (int i = 0; i < 8; i++)
                #pragma unroll
                for (int j = 0; j < 4; j++) s[m][i][j] = 0.f;

        #pragma unroll
        for (int ks = 0; ks < 4; ks++) {
            const int qc = ks*2 + aChH;
            uint32_t aQ[2][4];
            LDM4(aQ[0], sb + SWK(aRow0,      qc));
            LDM4(aQ[1], sb + SWK(aRow0 + 16, qc));
            const int cb = ks*2 + bChH;
            #pragma unroll
            for (int nt2 = 0; nt2 < 4; nt2++) {
                int r = bRowOff + nt2*16;
                uint32_t rk[4];
                LDM4(rk, uKf + SWK(r, cb));
                uint32_t b0[2] = {rk[0], rk[1]}, b1[2] = {rk[2], rk[3]};
                const int nA = nt2*2, nB = nt2*2 + 1;
                MMAH(s[0][nA], aQ[0], b0); MMAH(s[0][nB], aQ[0], b1);
                MMAH(s[1][nA], aQ[1], b0); MMAH(s[1][nB], aQ[1], b1);
            }
        }

        #pragma unroll
        for (int kt2 = 0; kt2 < 4; kt2++) {
            uint32_t aP[2][4];
            #pragma unroll
            for (int m = 0; m < 2; m++) {
                aP[m][0] = pack_h2(s[m][2*kt2][0]*s[m][2*kt2][0],     s[m][2*kt2][1]*s[m][2*kt2][1]);
                aP[m][1] = pack_h2(s[m][2*kt2][2]*s[m][2*kt2][2],     s[m][2*kt2][3]*s[m][2*kt2][3]);
                aP[m][2] = pack_h2(s[m][2*kt2+1][0]*s[m][2*kt2+1][0], s[m][2*kt2+1][1]*s[m][2*kt2+1][1]);
                aP[m][3] = pack_h2(s[m][2*kt2+1][2]*s[m][2*kt2+1][2], s[m][2*kt2+1][3]*s[m][2*kt2+1][3]);
            }
            const int cb = kt2*2 + bChH;
            #pragma unroll
            for (int nt2 = 0; nt2 < 4; nt2++) {
                int r = bRowOff + nt2*16;
                uint32_t rv[4];
                LDM4(rv, uVf + SWK(r, cb));
                uint32_t b0[2] = {rv[0], rv[1]}, b1[2] = {rv[2], rv[3]};
                const int nA = nt2*2, nB = nt2*2 + 1;
                MMAH(o[0][nA], aP[0], b0); MMAH(o[0][nB], aP[0], b1);
                MMAH(o[1][nA], aP[1], b0); MMAH(o[1][nB], aP[1], b1);
            }
        }
    }

    // ctx epilogue: fp16 single, [b, s, DM]
    const int g = lane >> 2, tig = lane & 3;
    const int b_ = bh >> 4, h_ = bh & 15;
    #pragma unroll
    for (int mt = 0; mt < 2; mt++) {
        const int r0 = q0 + w*32 + mt*16 + g;
        #pragma unroll
        for (int rr = 0; rr < 2; rr++) {
            const int s_ = r0 + rr*8;
            const size_t ob = ((size_t)b_ * SEQ + s_) * DM + h_ * DK;
            #pragma unroll
            for (int nt = 0; nt < 8; nt++)
                *(uint32_t*)(cf + ob + nt*8 + tig*2) =
                    pack_h2(o[mt][nt][rr*2], o[mt][nt][rr*2+1]);
        }
    }
#undef A_LOADKV
}

// ---------------------------------------------------------------------------
extern "C" void kernel_launch(void* const* d_in, const int* in_sizes, int n_in,
                              void* d_out, int out_size)
{
    const float* Q    = (const float*)d_in[0];
    const float* K    = (const float*)d_in[1];
    const float* V    = (const float*)d_in[2];
    const float* Wq_w = (const float*)d_in[3];
    const float* Wq_b = (const float*)d_in[4];
    const float* Wk_w = (const float*)d_in[5];
    const float* Wk_b = (const float*)d_in[6];
    const float* Wv_w = (const float*)d_in[7];
    const float* Wv_b = (const float*)d_in[8];
    const float* Wo_w = (const float*)d_in[9];
    const float* Wo_b = (const float*)d_in[10];
    float* out = (float*)d_out;

    __nv_bfloat16* gb;
    cudaGetSymbolAddress((void**)&gb, g_buf);

    __half* xf[3] = { (__half*)(gb + OFF_XQ), (__half*)(gb + OFF_XK), (__half*)(gb + OFF_XV) };
    __half* wf[4];
    for (int i = 0; i < 4; i++) wf[i] = (__half*)(gb + OFF_W) + (size_t)i * NW;
    __half *qf = (__half*)(gb + OFF_QF);
    __half *kf = (__half*)(gb + OFF_KF);
    __half *vf = (__half*)(gb + OFF_VF);
    __half *cf = (__half*)(gb + OFF_CF);

    cudaFuncSetAttribute(gemm_mma, cudaFuncAttributeMaxDynamicSharedMemorySize, GEMM_SMEM);
    cudaFuncSetAttribute(attn_mma, cudaFuncAttributeMaxDynamicSharedMemorySize, ATTN_SMEM);

    ConvArgs ca;
    ca.s[0] = (const float4*)Q;    ca.o[0] = (uint4*)xf[0]; ca.nch[0] = NX/8;
    ca.s[1] = (const float4*)K;    ca.o[1] = (uint4*)xf[1]; ca.nch[1] = NX/8;
    ca.s[2] = (const float4*)V;    ca.o[2] = (uint4*)xf[2]; ca.nch[2] = NX/8;
    ca.s[3] = (const float4*)Wq_w; ca.o[3] = (uint4*)wf[0]; ca.nch[3] = NW/8;
    ca.s[4] = (const float4*)Wk_w; ca.o[4] = (uint4*)wf[1]; ca.nch[4] = NW/8;
    ca.s[5] = (const float4*)Wv_w; ca.o[5] = (uint4*)wf[2]; ca.nch[5] = NW/8;
    ca.s[6] = (const float4*)Wo_w; ca.o[6] = (uint4*)wf[3]; ca.nch[6] = NW/8;
    conv_multi<<<dim3(NX/8/256, 7), 256>>>(ca);

    GemmArgs gqkv;
    gqkv.ah[0] = xf[0]; gqkv.wf[0] = wf[0];
    gqkv.bias[0] = Wq_b; gqkv.yf[0] = nullptr; gqkv.yh[0] = qf; gqkv.mode[0] = 3;
    gqkv.ah[1] = xf[1]; gqkv.wf[1] = wf[1];
    gqkv.bias[1] = Wk_b; gqkv.yf[1] = nullptr; gqkv.yh[1] = kf; gqkv.mode[1] = 3;
    gqkv.ah[2] = xf[2]; gqkv.wf[2] = wf[2];
    gqkv.bias[2] = Wv_b; gqkv.yf[2] = nullptr; gqkv.yh[2] = vf; gqkv.mode[2] = 1;
    gemm_mma<<<dim3(DM/128, MTOT/128, 3), 256, GEMM_SMEM>>>(gqkv);

    dim3 agrid(SEQ/128, NBH);
    attn_mma<<<agrid, 128, ATTN_SMEM>>>(qf, kf, vf, cf);

    GemmArgs go;
    go.ah[0] = cf; go.wf[0] = wf[3];
    go.bias[0] = Wo_b; go.yf[0] = out; go.yh[0] = nullptr; go.mode[0] = 0;
    go.ah[1] = go.ah[0]; go.wf[1] = go.wf[0];
    go.bias[1] = go.bias[0]; go.yf[1] = go.yf[0]; go.yh[1] = nullptr; go.mode[1] = 0;
    go.ah[2] = go.ah[0]; go.wf[2] = go.wf[0];
    go.bias[2] = go.bias[0]; go.yf[2] = go.yf[0]; go.yh[2] = nullptr; go.mode[2] = 0;
    gemm_mma<<<dim3(DM/128, MTOT/128, 1), 256, GEMM_SMEM>>>(go);
}